// round 7
// baseline (speedup 1.0000x reference)
#include <cuda_runtime.h>
#include <cuda_fp16.h>

#define NN   100000
#define EE   1600000
#define HALF (NN/2)
#define SCAN_BLOCKS 98   // 98*1024 = 100352 >= NN

// ---------------- scratch (device globals; allocation-free) ----------------
__device__ float  g_xw[(size_t)NN * 128];   // x@W fp32 (self terms; layer2 uses first NN*64)
__device__ __half g_xwh[(size_t)NN * 128];  // fp16 copy for gather (layer2 uses first NN*64)
__device__ float  g_h[(size_t)NN * 128];    // layer-1 activations (fp32)
__device__ float  g_deg1[NN], g_deg2[NN], g_dinv1[NN], g_dinv2[NN];   // deg zero-init OK (+1 folded)
__device__ int    g_hist[NN],  g_hist2[NN];                           // zeroed by scanA each call
__device__ int    g_off[NN + 1], g_off2[NN + 1];
__device__ int    g_cur[NN],   g_cur2[NN];
__device__ int    g_bsum[SCAN_BLOCKS], g_bsum2[SCAN_BLOCKS];
__device__ int2   g_e1[EE];                 // (src, ew*dinv1[src]) grouped by dst
__device__ int2   g_e2[EE];                 // (src, et*dinv2[src]) grouped by dst, et>0 only

// ---------------- packed f32x2 helpers (sm_103a FFMA2) ----------------
__device__ __forceinline__ unsigned long long pack_dup(float a) {
    unsigned long long r;
    asm("mov.b64 %0, {%1, %1};" : "=l"(r) : "r"(__float_as_uint(a)));
    return r;
}
__device__ __forceinline__ unsigned long long pack2(float x, float y) {
    unsigned long long r;
    asm("mov.b64 %0, {%1, %2};" : "=l"(r) : "r"(__float_as_uint(x)), "r"(__float_as_uint(y)));
    return r;
}
__device__ __forceinline__ float2 unpack2(unsigned long long v) {
    unsigned int lo, hi;
    asm("mov.b64 {%0, %1}, %2;" : "=r"(lo), "=r"(hi) : "l"(v));
    return make_float2(__uint_as_float(lo), __uint_as_float(hi));
}
__device__ __forceinline__ void fma2(unsigned long long& d, unsigned long long a, unsigned long long b) {
    asm("fma.rn.f32x2 %0, %1, %2, %0;" : "+l"(d) : "l"(a), "l"(b));
}
__device__ __forceinline__ unsigned int h2_from_f2(float lo, float hi) {
    __half2 h = __floats2half2_rn(lo, hi);
    return *reinterpret_cast<unsigned int*>(&h);
}

// ---------------- CSR build ----------------
__global__ void k_hist(const int* __restrict__ ei, const float* __restrict__ w,
                       const int* __restrict__ et) {
    int e = blockIdx.x * 256 + threadIdx.x;
    if (e < EE) {
        int dst = ei[EE + e];
        int t = et[e];
        atomicAdd(&g_hist[dst], 1);
        if (t > 0) {
            atomicAdd(&g_hist2[dst], 1);
            atomicAdd(&g_deg2[dst], (float)t);
        }
        atomicAdd(&g_deg1[dst], w[e]);
    }
}

__device__ __forceinline__ int warp_incl_scan(int v, int lane) {
    int x = v;
#pragma unroll
    for (int o = 1; o < 32; o <<= 1) {
        int y = __shfl_up_sync(0xffffffffu, x, o);
        if (lane >= o) x += y;
    }
    return x;
}

// ---- scan phase 1: scan both hist arrays; compute dinv (+1 self); self-clean ----
__global__ void k_scanA() {
    __shared__ int wsum[32], wsum2[32];
    const int tid = threadIdx.x;
    const int lane = tid & 31, wid = tid >> 5;
    int i = blockIdx.x * 1024 + tid;
    int v1 = 0, v2 = 0;
    if (i < NN) {
        v1 = g_hist[i]; v2 = g_hist2[i];
        g_hist[i] = 0;  g_hist2[i] = 0;            // clean for next call
        float d1 = g_deg1[i], d2 = g_deg2[i];
        g_deg1[i] = 0.f; g_deg2[i] = 0.f;          // clean for next call
        g_dinv1[i] = rsqrtf(d1 + 1.0f);            // self-loop weight 1 folded here
        g_dinv2[i] = rsqrtf(d2 + 1.0f);
    }
    int x1 = warp_incl_scan(v1, lane);
    int x2 = warp_incl_scan(v2, lane);
    if (lane == 31) { wsum[wid] = x1; wsum2[wid] = x2; }
    __syncthreads();
    if (wid == 0) {
        int s1 = warp_incl_scan(wsum[lane], lane);
        int s2 = warp_incl_scan(wsum2[lane], lane);
        wsum[lane] = s1; wsum2[lane] = s2;
    }
    __syncthreads();
    int e1 = (x1 - v1) + ((wid > 0) ? wsum[wid - 1] : 0);
    int e2 = (x2 - v2) + ((wid > 0) ? wsum2[wid - 1] : 0);
    if (i < NN) { g_off[i] = e1; g_off2[i] = e2; }
    if (tid == 0) { g_bsum[blockIdx.x] = wsum[31]; g_bsum2[blockIdx.x] = wsum2[31]; }
}

// ---- scan phase 2 ----
__global__ void k_scanB() {
    __shared__ int ws[4], ws2[4];
    const int tid = threadIdx.x;                 // 128 threads
    const int lane = tid & 31, wid = tid >> 5;
    int v1 = (tid < SCAN_BLOCKS) ? g_bsum[tid] : 0;
    int v2 = (tid < SCAN_BLOCKS) ? g_bsum2[tid] : 0;
    int x1 = warp_incl_scan(v1, lane);
    int x2 = warp_incl_scan(v2, lane);
    if (lane == 31) { ws[wid] = x1; ws2[wid] = x2; }
    __syncthreads();
    int add1 = 0, add2 = 0;
#pragma unroll
    for (int w = 0; w < 4; w++) {
        add1 += (w < wid) ? ws[w] : 0;
        add2 += (w < wid) ? ws2[w] : 0;
    }
    if (tid < SCAN_BLOCKS) {
        g_bsum[tid]  = (x1 - v1) + add1;
        g_bsum2[tid] = (x2 - v2) + add2;
        if (tid == SCAN_BLOCKS - 1) {
            g_off[NN]  = x1 + add1;   // = EE
            g_off2[NN] = x2 + add2;   // = #nonzero-type edges
        }
    }
}

// ---- scan phase 3 ----
__global__ void k_scanC() {
    int i = blockIdx.x * 1024 + threadIdx.x;
    if (i < NN) {
        int o1 = g_off[i]  + g_bsum[i >> 10];
        int o2 = g_off2[i] + g_bsum2[i >> 10];
        g_off[i] = o1;  g_cur[i] = o1;
        g_off2[i] = o2; g_cur2[i] = o2;
    }
}

__global__ void k_fill(const int* __restrict__ ei, const float* __restrict__ w,
                       const int* __restrict__ et) {
    int e = blockIdx.x * 256 + threadIdx.x;
    if (e < EE) {
        int src = ei[e];
        int dst = ei[EE + e];
        int pos = atomicAdd(&g_cur[dst], 1);
        g_e1[pos] = make_int2(src, __float_as_int(w[e] * g_dinv1[src]));
        int t = et[e];
        if (t > 0) {
            int pos2 = atomicAdd(&g_cur2[dst], 1);
            g_e2[pos2] = make_int2(src, __float_as_int((float)t * g_dinv2[src]));
        }
    }
}

// ---------------- GEMM1: g_xw = x @ W1 (fp32) + fp16 copy ----------------
// 128 threads, tile 64 rows x 128 cols, thread = 8 rows (4 pairs) x 8 cols.
#define XS1 80   // k-major row stride (floats): 16B aligned, 2-way-ish conflicts on fill
__global__ void k_gemm1(const float* __restrict__ x, const float* __restrict__ W) {
    extern __shared__ float sm[];
    float* Ws = sm;               // 128*128
    float* Xs = sm + 128 * 128;   // 128 * XS1 (64 rows used)
    const int tid = threadIdx.x;
    const int rbase = blockIdx.x * 64;

    const float4* W4 = (const float4*)W;
    float4* Ws4 = (float4*)Ws;
#pragma unroll
    for (int i = 0; i < 32; i++) Ws4[i * 128 + tid] = W4[i * 128 + tid];

#pragma unroll
    for (int it = 0; it < 64; it++) {
        int idx = it * 128 + tid;          // 64*128 elements
        int r = idx >> 7, k = idx & 127;
        int row = rbase + r;
        Xs[k * XS1 + r] = (row < NN) ? x[(size_t)row * 128 + k] : 0.f;
    }
    __syncthreads();

    const int tx = tid & 15, ty = tid >> 4;    // 16 col-groups x 8 row-groups
    const int cb = tx * 8, rb = ty * 8;
    unsigned long long acc[4][8];
#pragma unroll
    for (int p = 0; p < 4; p++)
#pragma unroll
        for (int c = 0; c < 8; c++) acc[p][c] = 0ull;

#pragma unroll 2
    for (int k = 0; k < 128; k++) {
        const float* wrow = Ws + k * 128 + cb;
        float4 wA = *(const float4*)wrow;
        float4 wB = *(const float4*)(wrow + 4);
        unsigned long long wd[8];
        wd[0] = pack_dup(wA.x); wd[1] = pack_dup(wA.y);
        wd[2] = pack_dup(wA.z); wd[3] = pack_dup(wA.w);
        wd[4] = pack_dup(wB.x); wd[5] = pack_dup(wB.y);
        wd[6] = pack_dup(wB.z); wd[7] = pack_dup(wB.w);
        const float* xr = Xs + k * XS1 + rb;
        float4 xA = *(const float4*)xr;
        float4 xB = *(const float4*)(xr + 4);
        unsigned long long a[4];
        a[0] = pack2(xA.x, xA.y); a[1] = pack2(xA.z, xA.w);
        a[2] = pack2(xB.x, xB.y); a[3] = pack2(xB.z, xB.w);
#pragma unroll
        for (int p = 0; p < 4; p++)
#pragma unroll
            for (int c = 0; c < 8; c++)
                fma2(acc[p][c], a[p], wd[c]);
    }

#pragma unroll
    for (int p = 0; p < 4; p++) {
        float lo[8], hi[8];
#pragma unroll
        for (int c = 0; c < 8; c++) {
            float2 t = unpack2(acc[p][c]);
            lo[c] = t.x; hi[c] = t.y;
        }
        int row0 = rbase + rb + 2 * p;
        if (row0 < NN) {
            *(float4*)&g_xw[(size_t)row0 * 128 + cb]     = make_float4(lo[0], lo[1], lo[2], lo[3]);
            *(float4*)&g_xw[(size_t)row0 * 128 + cb + 4] = make_float4(lo[4], lo[5], lo[6], lo[7]);
            uint4 hv;
            hv.x = h2_from_f2(lo[0], lo[1]); hv.y = h2_from_f2(lo[2], lo[3]);
            hv.z = h2_from_f2(lo[4], lo[5]); hv.w = h2_from_f2(lo[6], lo[7]);
            *(uint4*)&g_xwh[(size_t)row0 * 128 + cb] = hv;
        }
        int row1 = row0 + 1;
        if (row1 < NN) {
            *(float4*)&g_xw[(size_t)row1 * 128 + cb]     = make_float4(hi[0], hi[1], hi[2], hi[3]);
            *(float4*)&g_xw[(size_t)row1 * 128 + cb + 4] = make_float4(hi[4], hi[5], hi[6], hi[7]);
            uint4 hv;
            hv.x = h2_from_f2(hi[0], hi[1]); hv.y = h2_from_f2(hi[2], hi[3]);
            hv.z = h2_from_f2(hi[4], hi[5]); hv.w = h2_from_f2(hi[6], hi[7]);
            *(uint4*)&g_xwh[(size_t)row1 * 128 + cb] = hv;
        }
    }
}

// ---------------- GEMM2: g_xw[:,0:64] = h @ W2 (fp32) + fp16 copy ----------------
// 128 threads, tile 128 rows x 64 cols, thread = 8 rows (4 pairs) x 8 cols.
#define XS2 144   // k-major row stride (floats) for 128-row tile
__global__ void k_gemm2(const float* __restrict__ W) {
    extern __shared__ float sm[];
    float* Ws = sm;               // 128*64
    float* Xs = sm + 128 * 64;    // 128 * XS2 (128 rows used)
    const int tid = threadIdx.x;
    const int rbase = blockIdx.x * 128;

    const float4* W4 = (const float4*)W;
    float4* Ws4 = (float4*)Ws;
#pragma unroll
    for (int i = 0; i < 16; i++) Ws4[i * 128 + tid] = W4[i * 128 + tid];

#pragma unroll
    for (int it = 0; it < 128; it++) {
        int idx = it * 128 + tid;          // 128*128 elements
        int r = idx >> 7, k = idx & 127;
        int row = rbase + r;
        Xs[k * XS2 + r] = (row < NN) ? g_h[(size_t)row * 128 + k] : 0.f;
    }
    __syncthreads();

    const int tx = tid & 7, ty = tid >> 3;     // 8 col-groups x 16 row-groups
    const int cb = tx * 8, rb = ty * 8;
    unsigned long long acc[4][8];
#pragma unroll
    for (int p = 0; p < 4; p++)
#pragma unroll
        for (int c = 0; c < 8; c++) acc[p][c] = 0ull;

#pragma unroll 2
    for (int k = 0; k < 128; k++) {
        const float* wrow = Ws + k * 64 + cb;
        float4 wA = *(const float4*)wrow;
        float4 wB = *(const float4*)(wrow + 4);
        unsigned long long wd[8];
        wd[0] = pack_dup(wA.x); wd[1] = pack_dup(wA.y);
        wd[2] = pack_dup(wA.z); wd[3] = pack_dup(wA.w);
        wd[4] = pack_dup(wB.x); wd[5] = pack_dup(wB.y);
        wd[6] = pack_dup(wB.z); wd[7] = pack_dup(wB.w);
        const float* xr = Xs + k * XS2 + rb;
        float4 xA = *(const float4*)xr;
        float4 xB = *(const float4*)(xr + 4);
        unsigned long long a[4];
        a[0] = pack2(xA.x, xA.y); a[1] = pack2(xA.z, xA.w);
        a[2] = pack2(xB.x, xB.y); a[3] = pack2(xB.z, xB.w);
#pragma unroll
        for (int p = 0; p < 4; p++)
#pragma unroll
            for (int c = 0; c < 8; c++)
                fma2(acc[p][c], a[p], wd[c]);
    }

#pragma unroll
    for (int p = 0; p < 4; p++) {
        float lo[8], hi[8];
#pragma unroll
        for (int c = 0; c < 8; c++) {
            float2 t = unpack2(acc[p][c]);
            lo[c] = t.x; hi[c] = t.y;
        }
        int row0 = rbase + rb + 2 * p;
        if (row0 < NN) {
            *(float4*)&g_xw[(size_t)row0 * 64 + cb]     = make_float4(lo[0], lo[1], lo[2], lo[3]);
            *(float4*)&g_xw[(size_t)row0 * 64 + cb + 4] = make_float4(lo[4], lo[5], lo[6], lo[7]);
            uint4 hv;
            hv.x = h2_from_f2(lo[0], lo[1]); hv.y = h2_from_f2(lo[2], lo[3]);
            hv.z = h2_from_f2(lo[4], lo[5]); hv.w = h2_from_f2(lo[6], lo[7]);
            *(uint4*)&g_xwh[(size_t)row0 * 64 + cb] = hv;
        }
        int row1 = row0 + 1;
        if (row1 < NN) {
            *(float4*)&g_xw[(size_t)row1 * 64 + cb]     = make_float4(hi[0], hi[1], hi[2], hi[3]);
            *(float4*)&g_xw[(size_t)row1 * 64 + cb + 4] = make_float4(hi[4], hi[5], hi[6], hi[7]);
            uint4 hv;
            hv.x = h2_from_f2(hi[0], hi[1]); hv.y = h2_from_f2(hi[2], hi[3]);
            hv.z = h2_from_f2(hi[4], hi[5]); hv.w = h2_from_f2(hi[6], hi[7]);
            *(uint4*)&g_xwh[(size_t)row1 * 64 + cb] = hv;
        }
    }
}

// ---------------- gather layer 1: warp per dst node, 128 ch; fp16 neighbors ----------------
__global__ void k_gather1(const float* __restrict__ b, const float* __restrict__ al) {
    int gid = blockIdx.x * 256 + threadIdx.x;   // NN*32 threads exactly
    int node = gid >> 5;
    int lane = gid & 31;
    int beg = g_off[node], end = g_off[node + 1];
    float s = g_dinv1[node];

    // self loop (fp32): xw[node]*dinv^2; one factor here, one in epilogue
    float4 acc = *(const float4*)&g_xw[(size_t)node * 128 + lane * 4];
    acc.x *= s; acc.y *= s; acc.z *= s; acc.w *= s;

    int i = beg;
    for (; i + 3 < end; i += 4) {
        int2 e0 = g_e1[i], e1 = g_e1[i + 1], e2 = g_e1[i + 2], e3 = g_e1[i + 3];
        uint2 u0 = *(const uint2*)&g_xwh[(size_t)e0.x * 128 + lane * 4];
        uint2 u1 = *(const uint2*)&g_xwh[(size_t)e1.x * 128 + lane * 4];
        uint2 u2 = *(const uint2*)&g_xwh[(size_t)e2.x * 128 + lane * 4];
        uint2 u3 = *(const uint2*)&g_xwh[(size_t)e3.x * 128 + lane * 4];
        float w0 = __int_as_float(e0.y), w1 = __int_as_float(e1.y);
        float w2 = __int_as_float(e2.y), w3 = __int_as_float(e3.y);
        float2 p0 = __half22float2(*(__half2*)&u0.x), q0 = __half22float2(*(__half2*)&u0.y);
        float2 p1 = __half22float2(*(__half2*)&u1.x), q1 = __half22float2(*(__half2*)&u1.y);
        float2 p2 = __half22float2(*(__half2*)&u2.x), q2 = __half22float2(*(__half2*)&u2.y);
        float2 p3 = __half22float2(*(__half2*)&u3.x), q3 = __half22float2(*(__half2*)&u3.y);
        acc.x += w0 * p0.x + w1 * p1.x + w2 * p2.x + w3 * p3.x;
        acc.y += w0 * p0.y + w1 * p1.y + w2 * p2.y + w3 * p3.y;
        acc.z += w0 * q0.x + w1 * q1.x + w2 * q2.x + w3 * q3.x;
        acc.w += w0 * q0.y + w1 * q1.y + w2 * q2.y + w3 * q3.y;
    }
    for (; i < end; i++) {
        int2 e0 = g_e1[i];
        uint2 u0 = *(const uint2*)&g_xwh[(size_t)e0.x * 128 + lane * 4];
        float w0 = __int_as_float(e0.y);
        float2 p0 = __half22float2(*(__half2*)&u0.x), q0 = __half22float2(*(__half2*)&u0.y);
        acc.x += w0 * p0.x; acc.y += w0 * p0.y;
        acc.z += w0 * q0.x; acc.w += w0 * q0.y;
    }

    float4 bb = *(const float4*)&b[lane * 4];
    float4 aa = *(const float4*)&al[lane * 4];
    acc.x = acc.x * s + bb.x; acc.y = acc.y * s + bb.y;
    acc.z = acc.z * s + bb.z; acc.w = acc.w * s + bb.w;
    acc.x = (acc.x >= 0.f) ? acc.x : aa.x * acc.x;
    acc.y = (acc.y >= 0.f) ? acc.y : aa.y * acc.y;
    acc.z = (acc.z >= 0.f) ? acc.z : aa.z * acc.z;
    acc.w = (acc.w >= 0.f) ? acc.w : aa.w * acc.w;
    *(float4*)&g_h[(size_t)node * 128 + lane * 4] = acc;
}

// ---------------- gather layer 2 fused with half-combine ----------------
__device__ __forceinline__ float4 gather2_node(int node, int l16) {
    int beg = g_off2[node], end = g_off2[node + 1];
    float s = g_dinv2[node];
    float4 acc = *(const float4*)&g_xw[(size_t)node * 64 + l16 * 4];
    acc.x *= s; acc.y *= s; acc.z *= s; acc.w *= s;

    int i = beg;
    for (; i + 3 < end; i += 4) {
        int2 e0 = g_e2[i], e1 = g_e2[i + 1], e2 = g_e2[i + 2], e3 = g_e2[i + 3];
        uint2 u0 = *(const uint2*)&g_xwh[(size_t)e0.x * 64 + l16 * 4];
        uint2 u1 = *(const uint2*)&g_xwh[(size_t)e1.x * 64 + l16 * 4];
        uint2 u2 = *(const uint2*)&g_xwh[(size_t)e2.x * 64 + l16 * 4];
        uint2 u3 = *(const uint2*)&g_xwh[(size_t)e3.x * 64 + l16 * 4];
        float w0 = __int_as_float(e0.y), w1 = __int_as_float(e1.y);
        float w2 = __int_as_float(e2.y), w3 = __int_as_float(e3.y);
        float2 p0 = __half22float2(*(__half2*)&u0.x), q0 = __half22float2(*(__half2*)&u0.y);
        float2 p1 = __half22float2(*(__half2*)&u1.x), q1 = __half22float2(*(__half2*)&u1.y);
        float2 p2 = __half22float2(*(__half2*)&u2.x), q2 = __half22float2(*(__half2*)&u2.y);
        float2 p3 = __half22float2(*(__half2*)&u3.x), q3 = __half22float2(*(__half2*)&u3.y);
        acc.x += w0 * p0.x + w1 * p1.x + w2 * p2.x + w3 * p3.x;
        acc.y += w0 * p0.y + w1 * p1.y + w2 * p2.y + w3 * p3.y;
        acc.z += w0 * q0.x + w1 * q1.x + w2 * q2.x + w3 * q3.x;
        acc.w += w0 * q0.y + w1 * q1.y + w2 * q2.y + w3 * q3.y;
    }
    for (; i < end; i++) {
        int2 e0 = g_e2[i];
        uint2 u0 = *(const uint2*)&g_xwh[(size_t)e0.x * 64 + l16 * 4];
        float w0 = __int_as_float(e0.y);
        float2 p0 = __half22float2(*(__half2*)&u0.x), q0 = __half22float2(*(__half2*)&u0.y);
        acc.x += w0 * p0.x; acc.y += w0 * p0.y;
        acc.z += w0 * q0.x; acc.w += w0 * q0.y;
    }
    acc.x *= s; acc.y *= s; acc.z *= s; acc.w *= s;
    return acc;
}

__global__ void k_gather2(const float* __restrict__ b, const float* __restrict__ al,
                          float* __restrict__ out) {
    int gid = blockIdx.x * 256 + threadIdx.x;   // HALF*16 threads exactly
    int i = gid >> 4;
    int l16 = gid & 15;

    float4 va = gather2_node(i, l16);
    float4 vb = gather2_node(i + HALF, l16);

    float4 bb = *(const float4*)&b[l16 * 4];
    float4 aa = *(const float4*)&al[l16 * 4];
    va.x += bb.x; va.y += bb.y; va.z += bb.z; va.w += bb.w;
    vb.x += bb.x; vb.y += bb.y; vb.z += bb.z; vb.w += bb.w;
    va.x = (va.x >= 0.f) ? va.x : aa.x * va.x;
    va.y = (va.y >= 0.f) ? va.y : aa.y * va.y;
    va.z = (va.z >= 0.f) ? va.z : aa.z * va.z;
    va.w = (va.w >= 0.f) ? va.w : aa.w * va.w;
    vb.x = (vb.x >= 0.f) ? vb.x : aa.x * vb.x;
    vb.y = (vb.y >= 0.f) ? vb.y : aa.y * vb.y;
    vb.z = (vb.z >= 0.f) ? vb.z : aa.z * vb.z;
    vb.w = (vb.w >= 0.f) ? vb.w : aa.w * vb.w;

    *(float4*)&out[(size_t)i * 64 + l16 * 4] =
        make_float4(0.5f * (va.x + vb.x), 0.5f * (va.y + vb.y),
                    0.5f * (va.z + vb.z), 0.5f * (va.w + vb.w));
}

// ---------------- launch ----------------
extern "C" void kernel_launch(void* const* d_in, const int* in_sizes, int n_in,
                              void* d_out, int out_size) {
    (void)in_sizes; (void)n_in; (void)out_size;
    const float* x   = (const float*)d_in[0];
    const int*   ei  = (const int*)d_in[1];
    const float* ew  = (const float*)d_in[2];
    const int*   et  = (const int*)d_in[3];
    const float* W1  = (const float*)d_in[4];
    const float* b1  = (const float*)d_in[5];
    const float* a1  = (const float*)d_in[6];
    const float* W2  = (const float*)d_in[7];
    const float* b2  = (const float*)d_in[8];
    const float* a2  = (const float*)d_in[9];
    float* out = (float*)d_out;

    const int smem1 = (128 * 128 + 128 * XS1) * sizeof(float);   // 106496
    const int smem2 = (128 * 64  + 128 * XS2) * sizeof(float);   // 106496
    cudaFuncSetAttribute(k_gemm1, cudaFuncAttributeMaxDynamicSharedMemorySize, smem1);
    cudaFuncSetAttribute(k_gemm2, cudaFuncAttributeMaxDynamicSharedMemorySize, smem2);

    static cudaStream_t s2 = nullptr;
    static cudaEvent_t evF = nullptr, evJ = nullptr;
    static bool tried = false;
    if (!tried) {
        tried = true;
        if (cudaStreamCreateWithFlags(&s2, cudaStreamNonBlocking) != cudaSuccess) s2 = nullptr;
        if (s2) {
            if (cudaEventCreateWithFlags(&evF, cudaEventDisableTiming) != cudaSuccess) { s2 = nullptr; }
            else if (cudaEventCreateWithFlags(&evJ, cudaEventDisableTiming) != cudaSuccess) { s2 = nullptr; }
        }
    }

    if (s2) {
        cudaEventRecord(evF, 0);
        cudaStreamWaitEvent(s2, evF, 0);
        k_hist <<<(EE + 255) / 256, 256, 0, s2>>>(ei, ew, et);
        k_scanA<<<SCAN_BLOCKS, 1024, 0, s2>>>();
        k_scanB<<<1, 128, 0, s2>>>();
        k_scanC<<<SCAN_BLOCKS, 1024, 0, s2>>>();
        k_fill <<<(EE + 255) / 256, 256, 0, s2>>>(ei, ew, et);
        cudaEventRecord(evJ, s2);

        k_gemm1<<<(NN + 63) / 64, 128, smem1>>>(x, W1);
        cudaStreamWaitEvent(0, evJ, 0);
    } else {
        k_hist <<<(EE + 255) / 256, 256>>>(ei, ew, et);
        k_scanA<<<SCAN_BLOCKS, 1024>>>();
        k_scanB<<<1, 128>>>();
        k_scanC<<<SCAN_BLOCKS, 1024>>>();
        k_fill <<<(EE + 255) / 256, 256>>>(ei, ew, et);
        k_gemm1<<<(NN + 63) / 64, 128, smem1>>>(x, W1);
    }

    // layer 1 aggregate
    k_gather1<<<NN * 32 / 256, 256>>>(b1, a1);

    // layer 2 (+ fused half-combine)
    k_gemm2<<<(NN + 127) / 128, 128, smem2>>>(W2);
    k_gather2<<<HALF * 16 / 256, 256>>>(b2, a2, out);
}

// round 8
// speedup vs baseline: 1.1195x; 1.1195x over previous
#include <cuda_runtime.h>
#include <cuda_fp16.h>

#define NN   100000
#define EE   1600000
#define HALF (NN/2)
#define SCAN_BLOCKS 98   // 98*1024 = 100352 >= NN

// ---------------- scratch (device globals; allocation-free) ----------------
__device__ float  g_xw[(size_t)NN * 128];   // x@W fp32 (self terms; layer2 uses first NN*64)
__device__ __half g_xwh[(size_t)NN * 128];  // fp16 copy for gather (layer2 uses first NN*64)
__device__ float  g_h[(size_t)NN * 128];    // layer-1 activations (fp32)
__device__ float  g_deg1[NN], g_deg2[NN], g_dinv1[NN], g_dinv2[NN];   // deg zero-init OK (+1 folded)
__device__ int    g_hist[NN],  g_hist2[NN];                           // zeroed by scanA each call
__device__ int    g_off[NN + 1], g_off2[NN + 1];
__device__ int    g_cur[NN],   g_cur2[NN];
__device__ int    g_bsum[SCAN_BLOCKS], g_bsum2[SCAN_BLOCKS];
__device__ int2   g_e1[EE];                 // (src, ew*dinv1[src]) grouped by dst
__device__ int2   g_e2[EE];                 // (src, et*dinv2[src]) grouped by dst, et>0 only

// ---------------- packed f32x2 helpers (sm_103a FFMA2) ----------------
__device__ __forceinline__ unsigned long long pack_dup(float a) {
    unsigned long long r;
    asm("mov.b64 %0, {%1, %1};" : "=l"(r) : "r"(__float_as_uint(a)));
    return r;
}
__device__ __forceinline__ unsigned long long pack2f(float2 v) {
    unsigned long long r;
    asm("mov.b64 %0, {%1, %2};" : "=l"(r) : "r"(__float_as_uint(v.x)), "r"(__float_as_uint(v.y)));
    return r;
}
__device__ __forceinline__ float2 unpack2(unsigned long long v) {
    unsigned int lo, hi;
    asm("mov.b64 {%0, %1}, %2;" : "=r"(lo), "=r"(hi) : "l"(v));
    return make_float2(__uint_as_float(lo), __uint_as_float(hi));
}
__device__ __forceinline__ void fma2(unsigned long long& d, unsigned long long a, unsigned long long b) {
    asm("fma.rn.f32x2 %0, %1, %2, %0;" : "+l"(d) : "l"(a), "l"(b));
}
__device__ __forceinline__ unsigned int h2_from_f2(float lo, float hi) {
    __half2 h = __floats2half2_rn(lo, hi);
    return *reinterpret_cast<unsigned int*>(&h);
}

// ---------------- CSR build ----------------
__global__ void k_hist(const int* __restrict__ ei, const float* __restrict__ w,
                       const int* __restrict__ et) {
    int e = blockIdx.x * 256 + threadIdx.x;
    if (e < EE) {
        int dst = ei[EE + e];
        int t = et[e];
        atomicAdd(&g_hist[dst], 1);
        if (t > 0) {
            atomicAdd(&g_hist2[dst], 1);
            atomicAdd(&g_deg2[dst], (float)t);
        }
        atomicAdd(&g_deg1[dst], w[e]);
    }
}

__device__ __forceinline__ int warp_incl_scan(int v, int lane) {
    int x = v;
#pragma unroll
    for (int o = 1; o < 32; o <<= 1) {
        int y = __shfl_up_sync(0xffffffffu, x, o);
        if (lane >= o) x += y;
    }
    return x;
}

// ---- scan phase 1: scan both hist arrays; compute dinv (+1 self); self-clean ----
__global__ void k_scanA() {
    __shared__ int wsum[32], wsum2[32];
    const int tid = threadIdx.x;
    const int lane = tid & 31, wid = tid >> 5;
    int i = blockIdx.x * 1024 + tid;
    int v1 = 0, v2 = 0;
    if (i < NN) {
        v1 = g_hist[i]; v2 = g_hist2[i];
        g_hist[i] = 0;  g_hist2[i] = 0;            // clean for next call
        float d1 = g_deg1[i], d2 = g_deg2[i];
        g_deg1[i] = 0.f; g_deg2[i] = 0.f;          // clean for next call
        g_dinv1[i] = rsqrtf(d1 + 1.0f);            // self-loop weight 1 folded here
        g_dinv2[i] = rsqrtf(d2 + 1.0f);
    }
    int x1 = warp_incl_scan(v1, lane);
    int x2 = warp_incl_scan(v2, lane);
    if (lane == 31) { wsum[wid] = x1; wsum2[wid] = x2; }
    __syncthreads();
    if (wid == 0) {
        int s1 = warp_incl_scan(wsum[lane], lane);
        int s2 = warp_incl_scan(wsum2[lane], lane);
        wsum[lane] = s1; wsum2[lane] = s2;
    }
    __syncthreads();
    int e1 = (x1 - v1) + ((wid > 0) ? wsum[wid - 1] : 0);
    int e2 = (x2 - v2) + ((wid > 0) ? wsum2[wid - 1] : 0);
    if (i < NN) { g_off[i] = e1; g_off2[i] = e2; }
    if (tid == 0) { g_bsum[blockIdx.x] = wsum[31]; g_bsum2[blockIdx.x] = wsum2[31]; }
}

// ---- scan phase 2 ----
__global__ void k_scanB() {
    __shared__ int ws[4], ws2[4];
    const int tid = threadIdx.x;                 // 128 threads
    const int lane = tid & 31, wid = tid >> 5;
    int v1 = (tid < SCAN_BLOCKS) ? g_bsum[tid] : 0;
    int v2 = (tid < SCAN_BLOCKS) ? g_bsum2[tid] : 0;
    int x1 = warp_incl_scan(v1, lane);
    int x2 = warp_incl_scan(v2, lane);
    if (lane == 31) { ws[wid] = x1; ws2[wid] = x2; }
    __syncthreads();
    int add1 = 0, add2 = 0;
#pragma unroll
    for (int w = 0; w < 4; w++) {
        add1 += (w < wid) ? ws[w] : 0;
        add2 += (w < wid) ? ws2[w] : 0;
    }
    if (tid < SCAN_BLOCKS) {
        g_bsum[tid]  = (x1 - v1) + add1;
        g_bsum2[tid] = (x2 - v2) + add2;
        if (tid == SCAN_BLOCKS - 1) {
            g_off[NN]  = x1 + add1;   // = EE
            g_off2[NN] = x2 + add2;   // = #nonzero-type edges
        }
    }
}

// ---- scan phase 3 ----
__global__ void k_scanC() {
    int i = blockIdx.x * 1024 + threadIdx.x;
    if (i < NN) {
        int o1 = g_off[i]  + g_bsum[i >> 10];
        int o2 = g_off2[i] + g_bsum2[i >> 10];
        g_off[i] = o1;  g_cur[i] = o1;
        g_off2[i] = o2; g_cur2[i] = o2;
    }
}

__global__ void k_fill(const int* __restrict__ ei, const float* __restrict__ w,
                       const int* __restrict__ et) {
    int e = blockIdx.x * 256 + threadIdx.x;
    if (e < EE) {
        int src = ei[e];
        int dst = ei[EE + e];
        int pos = atomicAdd(&g_cur[dst], 1);
        g_e1[pos] = make_int2(src, __float_as_int(w[e] * g_dinv1[src]));
        int t = et[e];
        if (t > 0) {
            int pos2 = atomicAdd(&g_cur2[dst], 1);
            g_e2[pos2] = make_int2(src, __float_as_int((float)t * g_dinv2[src]));
        }
    }
}

// ---------------- GEMM1 (R6-proven shape): g_xw = x @ W1 + fp16 copy ----------------
__global__ void k_gemm1(const float* __restrict__ x, const float* __restrict__ W) {
    extern __shared__ float sm[];
    float* Ws = sm;              // 128*128
    float* Xs = sm + 128 * 128;  // 128 * 66
    const int tid = threadIdx.x;
    const int rbase = blockIdx.x * 64;

    const float4* W4 = (const float4*)W;
    float4* Ws4 = (float4*)Ws;
#pragma unroll
    for (int i = 0; i < 16; i++) Ws4[i * 256 + tid] = W4[i * 256 + tid];

#pragma unroll
    for (int it = 0; it < 32; it++) {
        int idx = it * 256 + tid;
        int r = idx >> 7, k = idx & 127;
        int row = rbase + r;
        Xs[k * 66 + r] = (row < NN) ? x[(size_t)row * 128 + k] : 0.f;
    }
    __syncthreads();

    const int tx = tid & 31, ty = tid >> 5;
    const int cb = tx * 4, rb = ty * 8;
    unsigned long long acc[4][4];
#pragma unroll
    for (int p = 0; p < 4; p++)
#pragma unroll
        for (int c = 0; c < 4; c++) acc[p][c] = 0ull;

#pragma unroll 4
    for (int k = 0; k < 128; k++) {
        float4 w4 = *(const float4*)(Ws + k * 128 + cb);
        unsigned long long wd0 = pack_dup(w4.x), wd1 = pack_dup(w4.y),
                           wd2 = pack_dup(w4.z), wd3 = pack_dup(w4.w);
        const float* xrow = Xs + k * 66 + rb;
#pragma unroll
        for (int p = 0; p < 4; p++) {
            unsigned long long a2 = pack2f(*(const float2*)(xrow + 2 * p));
            fma2(acc[p][0], a2, wd0);
            fma2(acc[p][1], a2, wd1);
            fma2(acc[p][2], a2, wd2);
            fma2(acc[p][3], a2, wd3);
        }
    }

#pragma unroll
    for (int p = 0; p < 4; p++) {
        float2 c0 = unpack2(acc[p][0]), c1 = unpack2(acc[p][1]),
               c2 = unpack2(acc[p][2]), c3 = unpack2(acc[p][3]);
        int row0 = rbase + rb + 2 * p;
        if (row0 < NN) {
            float4 o = make_float4(c0.x, c1.x, c2.x, c3.x);
            *(float4*)&g_xw[(size_t)row0 * 128 + cb] = o;
            uint2 hv; hv.x = h2_from_f2(o.x, o.y); hv.y = h2_from_f2(o.z, o.w);
            *(uint2*)&g_xwh[(size_t)row0 * 128 + cb] = hv;
        }
        int row1 = row0 + 1;
        if (row1 < NN) {
            float4 o = make_float4(c0.y, c1.y, c2.y, c3.y);
            *(float4*)&g_xw[(size_t)row1 * 128 + cb] = o;
            uint2 hv; hv.x = h2_from_f2(o.x, o.y); hv.y = h2_from_f2(o.z, o.w);
            *(uint2*)&g_xwh[(size_t)row1 * 128 + cb] = hv;
        }
    }
}

// ---------------- GEMM2 (R6-proven shape): g_xw[:,0:64] = h @ W2 + fp16 copy ----------------
__global__ void k_gemm2(const float* __restrict__ W) {
    extern __shared__ float sm[];
    float* Ws = sm;              // 128*64
    float* Xs = sm + 128 * 64;   // 128 * 66
    const int tid = threadIdx.x;
    const int rbase = blockIdx.x * 64;

    const float4* W4 = (const float4*)W;
    float4* Ws4 = (float4*)Ws;
#pragma unroll
    for (int i = 0; i < 8; i++) Ws4[i * 256 + tid] = W4[i * 256 + tid];

#pragma unroll
    for (int it = 0; it < 32; it++) {
        int idx = it * 256 + tid;
        int r = idx >> 7, k = idx & 127;
        int row = rbase + r;
        Xs[k * 66 + r] = (row < NN) ? g_h[(size_t)row * 128 + k] : 0.f;
    }
    __syncthreads();

    const int tx = tid & 15, ty = tid >> 4;
    const int cb = tx * 4, rb = ty * 4;
    unsigned long long acc[2][4];
#pragma unroll
    for (int p = 0; p < 2; p++)
#pragma unroll
        for (int c = 0; c < 4; c++) acc[p][c] = 0ull;

#pragma unroll 4
    for (int k = 0; k < 128; k++) {
        float4 w4 = *(const float4*)(Ws + k * 64 + cb);
        unsigned long long wd0 = pack_dup(w4.x), wd1 = pack_dup(w4.y),
                           wd2 = pack_dup(w4.z), wd3 = pack_dup(w4.w);
        const float* xrow = Xs + k * 66 + rb;
#pragma unroll
        for (int p = 0; p < 2; p++) {
            unsigned long long a2 = pack2f(*(const float2*)(xrow + 2 * p));
            fma2(acc[p][0], a2, wd0);
            fma2(acc[p][1], a2, wd1);
            fma2(acc[p][2], a2, wd2);
            fma2(acc[p][3], a2, wd3);
        }
    }

#pragma unroll
    for (int p = 0; p < 2; p++) {
        float2 c0 = unpack2(acc[p][0]), c1 = unpack2(acc[p][1]),
               c2 = unpack2(acc[p][2]), c3 = unpack2(acc[p][3]);
        int row0 = rbase + rb + 2 * p;
        if (row0 < NN) {
            float4 o = make_float4(c0.x, c1.x, c2.x, c3.x);
            *(float4*)&g_xw[(size_t)row0 * 64 + cb] = o;
            uint2 hv; hv.x = h2_from_f2(o.x, o.y); hv.y = h2_from_f2(o.z, o.w);
            *(uint2*)&g_xwh[(size_t)row0 * 64 + cb] = hv;
        }
        int row1 = row0 + 1;
        if (row1 < NN) {
            float4 o = make_float4(c0.y, c1.y, c2.y, c3.y);
            *(float4*)&g_xw[(size_t)row1 * 64 + cb] = o;
            uint2 hv; hv.x = h2_from_f2(o.x, o.y); hv.y = h2_from_f2(o.z, o.w);
            *(uint2*)&g_xwh[(size_t)row1 * 64 + cb] = hv;
        }
    }
}

// ---------------- gather layer 1: TWO warps per dst node (64 ch each), 4-edge unroll ----------------
__global__ void k_gather1(const float* __restrict__ b, const float* __restrict__ al) {
    int gid = blockIdx.x * 256 + threadIdx.x;   // NN*64 threads exactly
    int node = gid >> 6;
    int pair = gid & 63;                        // which half2 pair (0..63) -> channels 2*pair, 2*pair+1
    int beg = g_off[node], end = g_off[node + 1];
    float s = g_dinv1[node];

    // self loop (fp32): xw[node]*dinv^2; one factor here, one in epilogue
    float2 acc = *(const float2*)&g_xw[(size_t)node * 128 + pair * 2];
    acc.x *= s; acc.y *= s;

    int i = beg;
    for (; i + 3 < end; i += 4) {
        int2 e0 = g_e1[i], e1 = g_e1[i + 1], e2 = g_e1[i + 2], e3 = g_e1[i + 3];
        unsigned int u0 = *(const unsigned int*)&g_xwh[(size_t)e0.x * 128 + pair * 2];
        unsigned int u1 = *(const unsigned int*)&g_xwh[(size_t)e1.x * 128 + pair * 2];
        unsigned int u2 = *(const unsigned int*)&g_xwh[(size_t)e2.x * 128 + pair * 2];
        unsigned int u3 = *(const unsigned int*)&g_xwh[(size_t)e3.x * 128 + pair * 2];
        float w0 = __int_as_float(e0.y), w1 = __int_as_float(e1.y);
        float w2 = __int_as_float(e2.y), w3 = __int_as_float(e3.y);
        float2 v0 = __half22float2(*(__half2*)&u0);
        float2 v1 = __half22float2(*(__half2*)&u1);
        float2 v2 = __half22float2(*(__half2*)&u2);
        float2 v3 = __half22float2(*(__half2*)&u3);
        acc.x += w0 * v0.x + w1 * v1.x + w2 * v2.x + w3 * v3.x;
        acc.y += w0 * v0.y + w1 * v1.y + w2 * v2.y + w3 * v3.y;
    }
    for (; i < end; i++) {
        int2 e0 = g_e1[i];
        unsigned int u0 = *(const unsigned int*)&g_xwh[(size_t)e0.x * 128 + pair * 2];
        float w0 = __int_as_float(e0.y);
        float2 v0 = __half22float2(*(__half2*)&u0);
        acc.x += w0 * v0.x; acc.y += w0 * v0.y;
    }

    float2 bb = *(const float2*)&b[pair * 2];
    float2 aa = *(const float2*)&al[pair * 2];
    acc.x = acc.x * s + bb.x; acc.y = acc.y * s + bb.y;
    acc.x = (acc.x >= 0.f) ? acc.x : aa.x * acc.x;
    acc.y = (acc.y >= 0.f) ? acc.y : aa.y * acc.y;
    *(float2*)&g_h[(size_t)node * 128 + pair * 2] = acc;
}

// ---------------- gather layer 2 fused with half-combine (4-edge unroll) ----------------
__device__ __forceinline__ float4 gather2_node(int node, int l16) {
    int beg = g_off2[node], end = g_off2[node + 1];
    float s = g_dinv2[node];
    float4 acc = *(const float4*)&g_xw[(size_t)node * 64 + l16 * 4];
    acc.x *= s; acc.y *= s; acc.z *= s; acc.w *= s;

    int i = beg;
    for (; i + 3 < end; i += 4) {
        int2 e0 = g_e2[i], e1 = g_e2[i + 1], e2 = g_e2[i + 2], e3 = g_e2[i + 3];
        uint2 u0 = *(const uint2*)&g_xwh[(size_t)e0.x * 64 + l16 * 4];
        uint2 u1 = *(const uint2*)&g_xwh[(size_t)e1.x * 64 + l16 * 4];
        uint2 u2 = *(const uint2*)&g_xwh[(size_t)e2.x * 64 + l16 * 4];
        uint2 u3 = *(const uint2*)&g_xwh[(size_t)e3.x * 64 + l16 * 4];
        float w0 = __int_as_float(e0.y), w1 = __int_as_float(e1.y);
        float w2 = __int_as_float(e2.y), w3 = __int_as_float(e3.y);
        float2 p0 = __half22float2(*(__half2*)&u0.x), q0 = __half22float2(*(__half2*)&u0.y);
        float2 p1 = __half22float2(*(__half2*)&u1.x), q1 = __half22float2(*(__half2*)&u1.y);
        float2 p2 = __half22float2(*(__half2*)&u2.x), q2 = __half22float2(*(__half2*)&u2.y);
        float2 p3 = __half22float2(*(__half2*)&u3.x), q3 = __half22float2(*(__half2*)&u3.y);
        acc.x += w0 * p0.x + w1 * p1.x + w2 * p2.x + w3 * p3.x;
        acc.y += w0 * p0.y + w1 * p1.y + w2 * p2.y + w3 * p3.y;
        acc.z += w0 * q0.x + w1 * q1.x + w2 * q2.x + w3 * q3.x;
        acc.w += w0 * q0.y + w1 * q1.y + w2 * q2.y + w3 * q3.y;
    }
    for (; i < end; i++) {
        int2 e0 = g_e2[i];
        uint2 u0 = *(const uint2*)&g_xwh[(size_t)e0.x * 64 + l16 * 4];
        float w0 = __int_as_float(e0.y);
        float2 p0 = __half22float2(*(__half2*)&u0.x), q0 = __half22float2(*(__half2*)&u0.y);
        acc.x += w0 * p0.x; acc.y += w0 * p0.y;
        acc.z += w0 * q0.x; acc.w += w0 * q0.y;
    }
    acc.x *= s; acc.y *= s; acc.z *= s; acc.w *= s;
    return acc;
}

__global__ void k_gather2(const float* __restrict__ b, const float* __restrict__ al,
                          float* __restrict__ out) {
    int gid = blockIdx.x * 256 + threadIdx.x;   // HALF*16 threads exactly
    int i = gid >> 4;
    int l16 = gid & 15;

    float4 va = gather2_node(i, l16);
    float4 vb = gather2_node(i + HALF, l16);

    float4 bb = *(const float4*)&b[l16 * 4];
    float4 aa = *(const float4*)&al[l16 * 4];
    va.x += bb.x; va.y += bb.y; va.z += bb.z; va.w += bb.w;
    vb.x += bb.x; vb.y += bb.y; vb.z += bb.z; vb.w += bb.w;
    va.x = (va.x >= 0.f) ? va.x : aa.x * va.x;
    va.y = (va.y >= 0.f) ? va.y : aa.y * va.y;
    va.z = (va.z >= 0.f) ? va.z : aa.z * va.z;
    va.w = (va.w >= 0.f) ? va.w : aa.w * va.w;
    vb.x = (vb.x >= 0.f) ? vb.x : aa.x * vb.x;
    vb.y = (vb.y >= 0.f) ? vb.y : aa.y * vb.y;
    vb.z = (vb.z >= 0.f) ? vb.z : aa.z * vb.z;
    vb.w = (vb.w >= 0.f) ? vb.w : aa.w * vb.w;

    *(float4*)&out[(size_t)i * 64 + l16 * 4] =
        make_float4(0.5f * (va.x + vb.x), 0.5f * (va.y + vb.y),
                    0.5f * (va.z + vb.z), 0.5f * (va.w + vb.w));
}

// ---------------- launch ----------------
extern "C" void kernel_launch(void* const* d_in, const int* in_sizes, int n_in,
                              void* d_out, int out_size) {
    (void)in_sizes; (void)n_in; (void)out_size;
    const float* x   = (const float*)d_in[0];
    const int*   ei  = (const int*)d_in[1];
    const float* ew  = (const float*)d_in[2];
    const int*   et  = (const int*)d_in[3];
    const float* W1  = (const float*)d_in[4];
    const float* b1  = (const float*)d_in[5];
    const float* a1  = (const float*)d_in[6];
    const float* W2  = (const float*)d_in[7];
    const float* b2  = (const float*)d_in[8];
    const float* a2  = (const float*)d_in[9];
    float* out = (float*)d_out;

    const int smem1 = (128 * 128 + 128 * 66) * sizeof(float);   // 99328
    const int smem2 = (128 * 64  + 128 * 66) * sizeof(float);   // 66560
    cudaFuncSetAttribute(k_gemm1, cudaFuncAttributeMaxDynamicSharedMemorySize, smem1);
    cudaFuncSetAttribute(k_gemm2, cudaFuncAttributeMaxDynamicSharedMemorySize, smem2);

    const int gemm_blocks = (NN + 63) / 64;

    static cudaStream_t s2 = nullptr;
    static cudaEvent_t evF = nullptr, evJ = nullptr;
    static bool tried = false;
    if (!tried) {
        tried = true;
        if (cudaStreamCreateWithFlags(&s2, cudaStreamNonBlocking) != cudaSuccess) s2 = nullptr;
        if (s2) {
            if (cudaEventCreateWithFlags(&evF, cudaEventDisableTiming) != cudaSuccess) { s2 = nullptr; }
            else if (cudaEventCreateWithFlags(&evJ, cudaEventDisableTiming) != cudaSuccess) { s2 = nullptr; }
        }
    }

    if (s2) {
        cudaEventRecord(evF, 0);
        cudaStreamWaitEvent(s2, evF, 0);
        k_hist <<<(EE + 255) / 256, 256, 0, s2>>>(ei, ew, et);
        k_scanA<<<SCAN_BLOCKS, 1024, 0, s2>>>();
        k_scanB<<<1, 128, 0, s2>>>();
        k_scanC<<<SCAN_BLOCKS, 1024, 0, s2>>>();
        k_fill <<<(EE + 255) / 256, 256, 0, s2>>>(ei, ew, et);
        cudaEventRecord(evJ, s2);

        k_gemm1<<<gemm_blocks, 256, smem1>>>(x, W1);
        cudaStreamWaitEvent(0, evJ, 0);
    } else {
        k_hist <<<(EE + 255) / 256, 256>>>(ei, ew, et);
        k_scanA<<<SCAN_BLOCKS, 1024>>>();
        k_scanB<<<1, 128>>>();
        k_scanC<<<SCAN_BLOCKS, 1024>>>();
        k_fill <<<(EE + 255) / 256, 256>>>(ei, ew, et);
        k_gemm1<<<gemm_blocks, 256, smem1>>>(x, W1);
    }

    // layer 1 aggregate (2 warps per node)
    k_gather1<<<NN * 64 / 256, 256>>>(b1, a1);

    // layer 2 (+ fused half-combine)
    k_gemm2<<<gemm_blocks, 256, smem2>>>(W2);
    k_gather2<<<HALF * 16 / 256, 256>>>(b2, a2, out);
}

// round 9
// speedup vs baseline: 1.1669x; 1.0424x over previous
#include <cuda_runtime.h>
#include <cuda_fp16.h>

#define NN   100000
#define EE   1600000
#define HALF (NN/2)
#define SCAN_BLOCKS 98   // 98*1024 = 100352 >= NN

// ---------------- scratch (device globals; allocation-free) ----------------
__device__ float  g_xw[(size_t)NN * 128];   // x@W fp32 (self terms; layer2 uses first NN*64)
__device__ __half g_xwh[(size_t)NN * 128];  // fp16 copy for gather (layer2 uses first NN*64)
__device__ float  g_h[(size_t)NN * 128];    // layer-1 activations (fp32)
__device__ float  g_deg1[NN], g_deg2[NN], g_dinv1[NN], g_dinv2[NN];   // deg zero-init OK (+1 folded)
__device__ int    g_hist[NN],  g_hist2[NN];                           // zeroed by scanA each call
__device__ int    g_off[NN + 1], g_off2[NN + 1];
__device__ int    g_cur[NN],   g_cur2[NN];
__device__ int    g_bsum[SCAN_BLOCKS], g_bsum2[SCAN_BLOCKS];
__device__ int2   g_e1[EE];                 // (src, ew*dinv1[src]) grouped by dst
__device__ int2   g_e2[EE];                 // (src, et*dinv2[src]) grouped by dst, et>0 only

// ---------------- packed f32x2 helpers (sm_103a FFMA2) ----------------
__device__ __forceinline__ unsigned long long pack_dup(float a) {
    unsigned long long r;
    asm("mov.b64 %0, {%1, %1};" : "=l"(r) : "r"(__float_as_uint(a)));
    return r;
}
__device__ __forceinline__ unsigned long long pack2f(float2 v) {
    unsigned long long r;
    asm("mov.b64 %0, {%1, %2};" : "=l"(r) : "r"(__float_as_uint(v.x)), "r"(__float_as_uint(v.y)));
    return r;
}
__device__ __forceinline__ float2 unpack2(unsigned long long v) {
    unsigned int lo, hi;
    asm("mov.b64 {%0, %1}, %2;" : "=r"(lo), "=r"(hi) : "l"(v));
    return make_float2(__uint_as_float(lo), __uint_as_float(hi));
}
__device__ __forceinline__ void fma2(unsigned long long& d, unsigned long long a, unsigned long long b) {
    asm("fma.rn.f32x2 %0, %1, %2, %0;" : "+l"(d) : "l"(a), "l"(b));
}
__device__ __forceinline__ unsigned int h2_from_f2(float lo, float hi) {
    __half2 h = __floats2half2_rn(lo, hi);
    return *reinterpret_cast<unsigned int*>(&h);
}

// ---------------- CSR build ----------------
__global__ void k_hist(const int* __restrict__ ei, const float* __restrict__ w,
                       const int* __restrict__ et) {
    int e = blockIdx.x * 256 + threadIdx.x;
    if (e < EE) {
        int dst = ei[EE + e];
        int t = et[e];
        atomicAdd(&g_hist[dst], 1);
        if (t > 0) {
            atomicAdd(&g_hist2[dst], 1);
            atomicAdd(&g_deg2[dst], (float)t);
        }
        atomicAdd(&g_deg1[dst], w[e]);
    }
}

__device__ __forceinline__ int warp_incl_scan(int v, int lane) {
    int x = v;
#pragma unroll
    for (int o = 1; o < 32; o <<= 1) {
        int y = __shfl_up_sync(0xffffffffu, x, o);
        if (lane >= o) x += y;
    }
    return x;
}

// ---- scan phase 1: scan both hist arrays; compute dinv (+1 self); self-clean ----
__global__ void k_scanA() {
    __shared__ int wsum[32], wsum2[32];
    const int tid = threadIdx.x;
    const int lane = tid & 31, wid = tid >> 5;
    int i = blockIdx.x * 1024 + tid;
    int v1 = 0, v2 = 0;
    if (i < NN) {
        v1 = g_hist[i]; v2 = g_hist2[i];
        g_hist[i] = 0;  g_hist2[i] = 0;            // clean for next call
        float d1 = g_deg1[i], d2 = g_deg2[i];
        g_deg1[i] = 0.f; g_deg2[i] = 0.f;          // clean for next call
        g_dinv1[i] = rsqrtf(d1 + 1.0f);            // self-loop weight 1 folded here
        g_dinv2[i] = rsqrtf(d2 + 1.0f);
    }
    int x1 = warp_incl_scan(v1, lane);
    int x2 = warp_incl_scan(v2, lane);
    if (lane == 31) { wsum[wid] = x1; wsum2[wid] = x2; }
    __syncthreads();
    if (wid == 0) {
        int s1 = warp_incl_scan(wsum[lane], lane);
        int s2 = warp_incl_scan(wsum2[lane], lane);
        wsum[lane] = s1; wsum2[lane] = s2;
    }
    __syncthreads();
    int e1 = (x1 - v1) + ((wid > 0) ? wsum[wid - 1] : 0);
    int e2 = (x2 - v2) + ((wid > 0) ? wsum2[wid - 1] : 0);
    if (i < NN) { g_off[i] = e1; g_off2[i] = e2; }
    if (tid == 0) { g_bsum[blockIdx.x] = wsum[31]; g_bsum2[blockIdx.x] = wsum2[31]; }
}

// ---- scan phase 2 ----
__global__ void k_scanB() {
    __shared__ int ws[4], ws2[4];
    const int tid = threadIdx.x;                 // 128 threads
    const int lane = tid & 31, wid = tid >> 5;
    int v1 = (tid < SCAN_BLOCKS) ? g_bsum[tid] : 0;
    int v2 = (tid < SCAN_BLOCKS) ? g_bsum2[tid] : 0;
    int x1 = warp_incl_scan(v1, lane);
    int x2 = warp_incl_scan(v2, lane);
    if (lane == 31) { ws[wid] = x1; ws2[wid] = x2; }
    __syncthreads();
    int add1 = 0, add2 = 0;
#pragma unroll
    for (int w = 0; w < 4; w++) {
        add1 += (w < wid) ? ws[w] : 0;
        add2 += (w < wid) ? ws2[w] : 0;
    }
    if (tid < SCAN_BLOCKS) {
        g_bsum[tid]  = (x1 - v1) + add1;
        g_bsum2[tid] = (x2 - v2) + add2;
        if (tid == SCAN_BLOCKS - 1) {
            g_off[NN]  = x1 + add1;   // = EE
            g_off2[NN] = x2 + add2;   // = #nonzero-type edges
        }
    }
}

// ---- scan phase 3 ----
__global__ void k_scanC() {
    int i = blockIdx.x * 1024 + threadIdx.x;
    if (i < NN) {
        int o1 = g_off[i]  + g_bsum[i >> 10];
        int o2 = g_off2[i] + g_bsum2[i >> 10];
        g_off[i] = o1;  g_cur[i] = o1;
        g_off2[i] = o2; g_cur2[i] = o2;
    }
}

__global__ void k_fill(const int* __restrict__ ei, const float* __restrict__ w,
                       const int* __restrict__ et) {
    int e = blockIdx.x * 256 + threadIdx.x;
    if (e < EE) {
        int src = ei[e];
        int dst = ei[EE + e];
        int pos = atomicAdd(&g_cur[dst], 1);
        g_e1[pos] = make_int2(src, __float_as_int(w[e] * g_dinv1[src]));
        int t = et[e];
        if (t > 0) {
            int pos2 = atomicAdd(&g_cur2[dst], 1);
            g_e2[pos2] = make_int2(src, __float_as_int((float)t * g_dinv2[src]));
        }
    }
}

// ---------------- GEMM1 (R6-proven shape): g_xw = x @ W1 + fp16 copy ----------------
__global__ void k_gemm1(const float* __restrict__ x, const float* __restrict__ W) {
    extern __shared__ float sm[];
    float* Ws = sm;              // 128*128
    float* Xs = sm + 128 * 128;  // 128 * 66
    const int tid = threadIdx.x;
    const int rbase = blockIdx.x * 64;

    const float4* W4 = (const float4*)W;
    float4* Ws4 = (float4*)Ws;
#pragma unroll
    for (int i = 0; i < 16; i++) Ws4[i * 256 + tid] = W4[i * 256 + tid];

#pragma unroll
    for (int it = 0; it < 32; it++) {
        int idx = it * 256 + tid;
        int r = idx >> 7, k = idx & 127;
        int row = rbase + r;
        Xs[k * 66 + r] = (row < NN) ? x[(size_t)row * 128 + k] : 0.f;
    }
    __syncthreads();

    const int tx = tid & 31, ty = tid >> 5;
    const int cb = tx * 4, rb = ty * 8;
    unsigned long long acc[4][4];
#pragma unroll
    for (int p = 0; p < 4; p++)
#pragma unroll
        for (int c = 0; c < 4; c++) acc[p][c] = 0ull;

#pragma unroll 4
    for (int k = 0; k < 128; k++) {
        float4 w4 = *(const float4*)(Ws + k * 128 + cb);
        unsigned long long wd0 = pack_dup(w4.x), wd1 = pack_dup(w4.y),
                           wd2 = pack_dup(w4.z), wd3 = pack_dup(w4.w);
        const float* xrow = Xs + k * 66 + rb;
#pragma unroll
        for (int p = 0; p < 4; p++) {
            unsigned long long a2 = pack2f(*(const float2*)(xrow + 2 * p));
            fma2(acc[p][0], a2, wd0);
            fma2(acc[p][1], a2, wd1);
            fma2(acc[p][2], a2, wd2);
            fma2(acc[p][3], a2, wd3);
        }
    }

#pragma unroll
    for (int p = 0; p < 4; p++) {
        float2 c0 = unpack2(acc[p][0]), c1 = unpack2(acc[p][1]),
               c2 = unpack2(acc[p][2]), c3 = unpack2(acc[p][3]);
        int row0 = rbase + rb + 2 * p;
        if (row0 < NN) {
            float4 o = make_float4(c0.x, c1.x, c2.x, c3.x);
            *(float4*)&g_xw[(size_t)row0 * 128 + cb] = o;
            uint2 hv; hv.x = h2_from_f2(o.x, o.y); hv.y = h2_from_f2(o.z, o.w);
            *(uint2*)&g_xwh[(size_t)row0 * 128 + cb] = hv;
        }
        int row1 = row0 + 1;
        if (row1 < NN) {
            float4 o = make_float4(c0.y, c1.y, c2.y, c3.y);
            *(float4*)&g_xw[(size_t)row1 * 128 + cb] = o;
            uint2 hv; hv.x = h2_from_f2(o.x, o.y); hv.y = h2_from_f2(o.z, o.w);
            *(uint2*)&g_xwh[(size_t)row1 * 128 + cb] = hv;
        }
    }
}

// ---------------- GEMM2 (R6-proven shape): g_xw[:,0:64] = h @ W2 + fp16 copy ----------------
__global__ void k_gemm2(const float* __restrict__ W) {
    extern __shared__ float sm[];
    float* Ws = sm;              // 128*64
    float* Xs = sm + 128 * 64;   // 128 * 66
    const int tid = threadIdx.x;
    const int rbase = blockIdx.x * 64;

    const float4* W4 = (const float4*)W;
    float4* Ws4 = (float4*)Ws;
#pragma unroll
    for (int i = 0; i < 8; i++) Ws4[i * 256 + tid] = W4[i * 256 + tid];

#pragma unroll
    for (int it = 0; it < 32; it++) {
        int idx = it * 256 + tid;
        int r = idx >> 7, k = idx & 127;
        int row = rbase + r;
        Xs[k * 66 + r] = (row < NN) ? g_h[(size_t)row * 128 + k] : 0.f;
    }
    __syncthreads();

    const int tx = tid & 15, ty = tid >> 4;
    const int cb = tx * 4, rb = ty * 4;
    unsigned long long acc[2][4];
#pragma unroll
    for (int p = 0; p < 2; p++)
#pragma unroll
        for (int c = 0; c < 4; c++) acc[p][c] = 0ull;

#pragma unroll 4
    for (int k = 0; k < 128; k++) {
        float4 w4 = *(const float4*)(Ws + k * 64 + cb);
        unsigned long long wd0 = pack_dup(w4.x), wd1 = pack_dup(w4.y),
                           wd2 = pack_dup(w4.z), wd3 = pack_dup(w4.w);
        const float* xrow = Xs + k * 66 + rb;
#pragma unroll
        for (int p = 0; p < 2; p++) {
            unsigned long long a2 = pack2f(*(const float2*)(xrow + 2 * p));
            fma2(acc[p][0], a2, wd0);
            fma2(acc[p][1], a2, wd1);
            fma2(acc[p][2], a2, wd2);
            fma2(acc[p][3], a2, wd3);
        }
    }

#pragma unroll
    for (int p = 0; p < 2; p++) {
        float2 c0 = unpack2(acc[p][0]), c1 = unpack2(acc[p][1]),
               c2 = unpack2(acc[p][2]), c3 = unpack2(acc[p][3]);
        int row0 = rbase + rb + 2 * p;
        if (row0 < NN) {
            float4 o = make_float4(c0.x, c1.x, c2.x, c3.x);
            *(float4*)&g_xw[(size_t)row0 * 64 + cb] = o;
            uint2 hv; hv.x = h2_from_f2(o.x, o.y); hv.y = h2_from_f2(o.z, o.w);
            *(uint2*)&g_xwh[(size_t)row0 * 64 + cb] = hv;
        }
        int row1 = row0 + 1;
        if (row1 < NN) {
            float4 o = make_float4(c0.y, c1.y, c2.y, c3.y);
            *(float4*)&g_xw[(size_t)row1 * 64 + cb] = o;
            uint2 hv; hv.x = h2_from_f2(o.x, o.y); hv.y = h2_from_f2(o.z, o.w);
            *(uint2*)&g_xwh[(size_t)row1 * 64 + cb] = hv;
        }
    }
}

// ---------------- gather layer 1: warp per dst node (uint2 loads), 4-edge unroll ----------------
__global__ void k_gather1(const float* __restrict__ b, const float* __restrict__ al) {
    int gid = blockIdx.x * 256 + threadIdx.x;   // NN*32 threads exactly
    int node = gid >> 5;
    int lane = gid & 31;
    int beg = g_off[node], end = g_off[node + 1];
    float s = g_dinv1[node];

    // self loop (fp32): xw[node]*dinv^2; one factor here, one in epilogue
    float4 acc = *(const float4*)&g_xw[(size_t)node * 128 + lane * 4];
    acc.x *= s; acc.y *= s; acc.z *= s; acc.w *= s;

    int i = beg;
    for (; i + 3 < end; i += 4) {
        int2 e0 = g_e1[i], e1 = g_e1[i + 1], e2 = g_e1[i + 2], e3 = g_e1[i + 3];
        uint2 u0 = *(const uint2*)&g_xwh[(size_t)e0.x * 128 + lane * 4];
        uint2 u1 = *(const uint2*)&g_xwh[(size_t)e1.x * 128 + lane * 4];
        uint2 u2 = *(const uint2*)&g_xwh[(size_t)e2.x * 128 + lane * 4];
        uint2 u3 = *(const uint2*)&g_xwh[(size_t)e3.x * 128 + lane * 4];
        float w0 = __int_as_float(e0.y), w1 = __int_as_float(e1.y);
        float w2 = __int_as_float(e2.y), w3 = __int_as_float(e3.y);
        float2 p0 = __half22float2(*(__half2*)&u0.x), q0 = __half22float2(*(__half2*)&u0.y);
        float2 p1 = __half22float2(*(__half2*)&u1.x), q1 = __half22float2(*(__half2*)&u1.y);
        float2 p2 = __half22float2(*(__half2*)&u2.x), q2 = __half22float2(*(__half2*)&u2.y);
        float2 p3 = __half22float2(*(__half2*)&u3.x), q3 = __half22float2(*(__half2*)&u3.y);
        acc.x += (w0 * p0.x + w1 * p1.x) + (w2 * p2.x + w3 * p3.x);
        acc.y += (w0 * p0.y + w1 * p1.y) + (w2 * p2.y + w3 * p3.y);
        acc.z += (w0 * q0.x + w1 * q1.x) + (w2 * q2.x + w3 * q3.x);
        acc.w += (w0 * q0.y + w1 * q1.y) + (w2 * q2.y + w3 * q3.y);
    }
    for (; i < end; i++) {
        int2 e0 = g_e1[i];
        uint2 u0 = *(const uint2*)&g_xwh[(size_t)e0.x * 128 + lane * 4];
        float w0 = __int_as_float(e0.y);
        float2 p0 = __half22float2(*(__half2*)&u0.x), q0 = __half22float2(*(__half2*)&u0.y);
        acc.x += w0 * p0.x; acc.y += w0 * p0.y;
        acc.z += w0 * q0.x; acc.w += w0 * q0.y;
    }

    float4 bb = *(const float4*)&b[lane * 4];
    float4 aa = *(const float4*)&al[lane * 4];
    acc.x = acc.x * s + bb.x; acc.y = acc.y * s + bb.y;
    acc.z = acc.z * s + bb.z; acc.w = acc.w * s + bb.w;
    acc.x = (acc.x >= 0.f) ? acc.x : aa.x * acc.x;
    acc.y = (acc.y >= 0.f) ? acc.y : aa.y * acc.y;
    acc.z = (acc.z >= 0.f) ? acc.z : aa.z * acc.z;
    acc.w = (acc.w >= 0.f) ? acc.w : aa.w * acc.w;
    *(float4*)&g_h[(size_t)node * 128 + lane * 4] = acc;
}

// ---------------- gather layer 2 fused with half-combine (4-edge unroll) ----------------
__device__ __forceinline__ float4 gather2_node(int node, int l16) {
    int beg = g_off2[node], end = g_off2[node + 1];
    float s = g_dinv2[node];
    float4 acc = *(const float4*)&g_xw[(size_t)node * 64 + l16 * 4];
    acc.x *= s; acc.y *= s; acc.z *= s; acc.w *= s;

    int i = beg;
    for (; i + 3 < end; i += 4) {
        int2 e0 = g_e2[i], e1 = g_e2[i + 1], e2 = g_e2[i + 2], e3 = g_e2[i + 3];
        uint2 u0 = *(const uint2*)&g_xwh[(size_t)e0.x * 64 + l16 * 4];
        uint2 u1 = *(const uint2*)&g_xwh[(size_t)e1.x * 64 + l16 * 4];
        uint2 u2 = *(const uint2*)&g_xwh[(size_t)e2.x * 64 + l16 * 4];
        uint2 u3 = *(const uint2*)&g_xwh[(size_t)e3.x * 64 + l16 * 4];
        float w0 = __int_as_float(e0.y), w1 = __int_as_float(e1.y);
        float w2 = __int_as_float(e2.y), w3 = __int_as_float(e3.y);
        float2 p0 = __half22float2(*(__half2*)&u0.x), q0 = __half22float2(*(__half2*)&u0.y);
        float2 p1 = __half22float2(*(__half2*)&u1.x), q1 = __half22float2(*(__half2*)&u1.y);
        float2 p2 = __half22float2(*(__half2*)&u2.x), q2 = __half22float2(*(__half2*)&u2.y);
        float2 p3 = __half22float2(*(__half2*)&u3.x), q3 = __half22float2(*(__half2*)&u3.y);
        acc.x += (w0 * p0.x + w1 * p1.x) + (w2 * p2.x + w3 * p3.x);
        acc.y += (w0 * p0.y + w1 * p1.y) + (w2 * p2.y + w3 * p3.y);
        acc.z += (w0 * q0.x + w1 * q1.x) + (w2 * q2.x + w3 * q3.x);
        acc.w += (w0 * q0.y + w1 * q1.y) + (w2 * q2.y + w3 * q3.y);
    }
    for (; i < end; i++) {
        int2 e0 = g_e2[i];
        uint2 u0 = *(const uint2*)&g_xwh[(size_t)e0.x * 64 + l16 * 4];
        float w0 = __int_as_float(e0.y);
        float2 p0 = __half22float2(*(__half2*)&u0.x), q0 = __half22float2(*(__half2*)&u0.y);
        acc.x += w0 * p0.x; acc.y += w0 * p0.y;
        acc.z += w0 * q0.x; acc.w += w0 * q0.y;
    }
    acc.x *= s; acc.y *= s; acc.z *= s; acc.w *= s;
    return acc;
}

__global__ void k_gather2(const float* __restrict__ b, const float* __restrict__ al,
                          float* __restrict__ out) {
    int gid = blockIdx.x * 256 + threadIdx.x;   // HALF*16 threads exactly
    int i = gid >> 4;
    int l16 = gid & 15;

    float4 va = gather2_node(i, l16);
    float4 vb = gather2_node(i + HALF, l16);

    float4 bb = *(const float4*)&b[l16 * 4];
    float4 aa = *(const float4*)&al[l16 * 4];
    va.x += bb.x; va.y += bb.y; va.z += bb.z; va.w += bb.w;
    vb.x += bb.x; vb.y += bb.y; vb.z += bb.z; vb.w += bb.w;
    va.x = (va.x >= 0.f) ? va.x : aa.x * va.x;
    va.y = (va.y >= 0.f) ? va.y : aa.y * va.y;
    va.z = (va.z >= 0.f) ? va.z : aa.z * va.z;
    va.w = (va.w >= 0.f) ? va.w : aa.w * va.w;
    vb.x = (vb.x >= 0.f) ? vb.x : aa.x * vb.x;
    vb.y = (vb.y >= 0.f) ? vb.y : aa.y * vb.y;
    vb.z = (vb.z >= 0.f) ? vb.z : aa.z * vb.z;
    vb.w = (vb.w >= 0.f) ? vb.w : aa.w * vb.w;

    *(float4*)&out[(size_t)i * 64 + l16 * 4] =
        make_float4(0.5f * (va.x + vb.x), 0.5f * (va.y + vb.y),
                    0.5f * (va.z + vb.z), 0.5f * (va.w + vb.w));
}

// ---------------- launch ----------------
extern "C" void kernel_launch(void* const* d_in, const int* in_sizes, int n_in,
                              void* d_out, int out_size) {
    (void)in_sizes; (void)n_in; (void)out_size;
    const float* x   = (const float*)d_in[0];
    const int*   ei  = (const int*)d_in[1];
    const float* ew  = (const float*)d_in[2];
    const int*   et  = (const int*)d_in[3];
    const float* W1  = (const float*)d_in[4];
    const float* b1  = (const float*)d_in[5];
    const float* a1  = (const float*)d_in[6];
    const float* W2  = (const float*)d_in[7];
    const float* b2  = (const float*)d_in[8];
    const float* a2  = (const float*)d_in[9];
    float* out = (float*)d_out;

    const int smem1 = (128 * 128 + 128 * 66) * sizeof(float);   // 99328
    const int smem2 = (128 * 64  + 128 * 66) * sizeof(float);   // 66560
    cudaFuncSetAttribute(k_gemm1, cudaFuncAttributeMaxDynamicSharedMemorySize, smem1);
    cudaFuncSetAttribute(k_gemm2, cudaFuncAttributeMaxDynamicSharedMemorySize, smem2);

    const int gemm_blocks = (NN + 63) / 64;

    static cudaStream_t s2 = nullptr;
    static cudaEvent_t evF = nullptr, evJ = nullptr;
    static bool tried = false;
    if (!tried) {
        tried = true;
        if (cudaStreamCreateWithFlags(&s2, cudaStreamNonBlocking) != cudaSuccess) s2 = nullptr;
        if (s2) {
            if (cudaEventCreateWithFlags(&evF, cudaEventDisableTiming) != cudaSuccess) { s2 = nullptr; }
            else if (cudaEventCreateWithFlags(&evJ, cudaEventDisableTiming) != cudaSuccess) { s2 = nullptr; }
        }
    }

    if (s2) {
        cudaEventRecord(evF, 0);
        cudaStreamWaitEvent(s2, evF, 0);
        k_hist <<<(EE + 255) / 256, 256, 0, s2>>>(ei, ew, et);
        k_scanA<<<SCAN_BLOCKS, 1024, 0, s2>>>();
        k_scanB<<<1, 128, 0, s2>>>();
        k_scanC<<<SCAN_BLOCKS, 1024, 0, s2>>>();
        k_fill <<<(EE + 255) / 256, 256, 0, s2>>>(ei, ew, et);
        cudaEventRecord(evJ, s2);

        k_gemm1<<<gemm_blocks, 256, smem1>>>(x, W1);
        cudaStreamWaitEvent(0, evJ, 0);
    } else {
        k_hist <<<(EE + 255) / 256, 256>>>(ei, ew, et);
        k_scanA<<<SCAN_BLOCKS, 1024>>>();
        k_scanB<<<1, 128>>>();
        k_scanC<<<SCAN_BLOCKS, 1024>>>();
        k_fill <<<(EE + 255) / 256, 256>>>(ei, ew, et);
        k_gemm1<<<gemm_blocks, 256, smem1>>>(x, W1);
    }

    // layer 1 aggregate
    k_gather1<<<NN * 32 / 256, 256>>>(b1, a1);

    // layer 2 (+ fused half-combine)
    k_gemm2<<<gemm_blocks, 256, smem2>>>(W2);
    k_gather2<<<HALF * 16 / 256, 256>>>(b2, a2, out);
}

// round 10
// speedup vs baseline: 1.1976x; 1.0263x over previous
#include <cuda_runtime.h>
#include <cuda_fp16.h>

#define NN   100000
#define EE   1600000
#define HALF (NN/2)
#define SCAN_BLOCKS 98   // 98*1024 = 100352 >= NN

// ---------------- scratch (device globals; allocation-free) ----------------
__device__ float  g_xw[(size_t)NN * 128];   // x@W fp32 (self terms; layer2 uses first NN*64)
__device__ __half g_xwh[(size_t)NN * 128];  // fp16 copy for gather (layer2 uses first NN*64)
__device__ __half g_hh[(size_t)NN * 128];   // layer-1 activations (fp16)
__device__ float  g_deg1[NN], g_deg2[NN], g_dinv1[NN], g_dinv2[NN];   // deg zero-init OK (+1 folded)
__device__ int    g_hist[NN],  g_hist2[NN];                           // zeroed by scanA each call
__device__ int    g_off[NN + 1], g_off2[NN + 1];
__device__ int    g_cur[NN],   g_cur2[NN];
__device__ int    g_bsum[SCAN_BLOCKS], g_bsum2[SCAN_BLOCKS];
__device__ int2   g_e1[EE];                 // (src, ew*dinv1[src]) grouped by dst
__device__ int2   g_e2[EE];                 // (src, et*dinv2[src]) grouped by dst, et>0 only

// ---------------- packed f32x2 helpers (sm_103a FFMA2) ----------------
__device__ __forceinline__ unsigned long long pack_dup(float a) {
    unsigned long long r;
    asm("mov.b64 %0, {%1, %1};" : "=l"(r) : "r"(__float_as_uint(a)));
    return r;
}
__device__ __forceinline__ unsigned long long pack2f(float2 v) {
    unsigned long long r;
    asm("mov.b64 %0, {%1, %2};" : "=l"(r) : "r"(__float_as_uint(v.x)), "r"(__float_as_uint(v.y)));
    return r;
}
__device__ __forceinline__ float2 unpack2(unsigned long long v) {
    unsigned int lo, hi;
    asm("mov.b64 {%0, %1}, %2;" : "=r"(lo), "=r"(hi) : "l"(v));
    return make_float2(__uint_as_float(lo), __uint_as_float(hi));
}
__device__ __forceinline__ void fma2(unsigned long long& d, unsigned long long a, unsigned long long b) {
    asm("fma.rn.f32x2 %0, %1, %2, %0;" : "+l"(d) : "l"(a), "l"(b));
}
__device__ __forceinline__ unsigned int h2_from_f2(float lo, float hi) {
    __half2 h = __floats2half2_rn(lo, hi);
    return *reinterpret_cast<unsigned int*>(&h);
}

// ---------------- CSR build ----------------
__global__ void k_hist(const int* __restrict__ ei, const float* __restrict__ w,
                       const int* __restrict__ et) {
    int e = blockIdx.x * 256 + threadIdx.x;
    if (e < EE) {
        int dst = ei[EE + e];
        int t = et[e];
        atomicAdd(&g_hist[dst], 1);
        if (t > 0) {
            atomicAdd(&g_hist2[dst], 1);
            atomicAdd(&g_deg2[dst], (float)t);
        }
        atomicAdd(&g_deg1[dst], w[e]);
    }
}

__device__ __forceinline__ int warp_incl_scan(int v, int lane) {
    int x = v;
#pragma unroll
    for (int o = 1; o < 32; o <<= 1) {
        int y = __shfl_up_sync(0xffffffffu, x, o);
        if (lane >= o) x += y;
    }
    return x;
}

// ---- scan phase 1: scan both hist arrays; compute dinv (+1 self); self-clean ----
__global__ void k_scanA() {
    __shared__ int wsum[32], wsum2[32];
    const int tid = threadIdx.x;
    const int lane = tid & 31, wid = tid >> 5;
    int i = blockIdx.x * 1024 + tid;
    int v1 = 0, v2 = 0;
    if (i < NN) {
        v1 = g_hist[i]; v2 = g_hist2[i];
        g_hist[i] = 0;  g_hist2[i] = 0;            // clean for next call
        float d1 = g_deg1[i], d2 = g_deg2[i];
        g_deg1[i] = 0.f; g_deg2[i] = 0.f;          // clean for next call
        g_dinv1[i] = rsqrtf(d1 + 1.0f);            // self-loop weight 1 folded here
        g_dinv2[i] = rsqrtf(d2 + 1.0f);
    }
    int x1 = warp_incl_scan(v1, lane);
    int x2 = warp_incl_scan(v2, lane);
    if (lane == 31) { wsum[wid] = x1; wsum2[wid] = x2; }
    __syncthreads();
    if (wid == 0) {
        int s1 = warp_incl_scan(wsum[lane], lane);
        int s2 = warp_incl_scan(wsum2[lane], lane);
        wsum[lane] = s1; wsum2[lane] = s2;
    }
    __syncthreads();
    int e1 = (x1 - v1) + ((wid > 0) ? wsum[wid - 1] : 0);
    int e2 = (x2 - v2) + ((wid > 0) ? wsum2[wid - 1] : 0);
    if (i < NN) { g_off[i] = e1; g_off2[i] = e2; }
    if (tid == 0) { g_bsum[blockIdx.x] = wsum[31]; g_bsum2[blockIdx.x] = wsum2[31]; }
}

// ---- scan phase 2 ----
__global__ void k_scanB() {
    __shared__ int ws[4], ws2[4];
    const int tid = threadIdx.x;                 // 128 threads
    const int lane = tid & 31, wid = tid >> 5;
    int v1 = (tid < SCAN_BLOCKS) ? g_bsum[tid] : 0;
    int v2 = (tid < SCAN_BLOCKS) ? g_bsum2[tid] : 0;
    int x1 = warp_incl_scan(v1, lane);
    int x2 = warp_incl_scan(v2, lane);
    if (lane == 31) { ws[wid] = x1; ws2[wid] = x2; }
    __syncthreads();
    int add1 = 0, add2 = 0;
#pragma unroll
    for (int w = 0; w < 4; w++) {
        add1 += (w < wid) ? ws[w] : 0;
        add2 += (w < wid) ? ws2[w] : 0;
    }
    if (tid < SCAN_BLOCKS) {
        g_bsum[tid]  = (x1 - v1) + add1;
        g_bsum2[tid] = (x2 - v2) + add2;
        if (tid == SCAN_BLOCKS - 1) {
            g_off[NN]  = x1 + add1;   // = EE
            g_off2[NN] = x2 + add2;   // = #nonzero-type edges
        }
    }
}

// ---- scan phase 3 ----
__global__ void k_scanC() {
    int i = blockIdx.x * 1024 + threadIdx.x;
    if (i < NN) {
        int o1 = g_off[i]  + g_bsum[i >> 10];
        int o2 = g_off2[i] + g_bsum2[i >> 10];
        g_off[i] = o1;  g_cur[i] = o1;
        g_off2[i] = o2; g_cur2[i] = o2;
    }
}

__global__ void k_fill(const int* __restrict__ ei, const float* __restrict__ w,
                       const int* __restrict__ et) {
    int e = blockIdx.x * 256 + threadIdx.x;
    if (e < EE) {
        int src = ei[e];
        int dst = ei[EE + e];
        int pos = atomicAdd(&g_cur[dst], 1);
        g_e1[pos] = make_int2(src, __float_as_int(w[e] * g_dinv1[src]));
        int t = et[e];
        if (t > 0) {
            int pos2 = atomicAdd(&g_cur2[dst], 1);
            g_e2[pos2] = make_int2(src, __float_as_int((float)t * g_dinv2[src]));
        }
    }
}

// ---------------- GEMM1 (R6-proven shape): g_xw = x @ W1 + fp16 copy ----------------
__global__ void k_gemm1(const float* __restrict__ x, const float* __restrict__ W) {
    extern __shared__ float sm[];
    float* Ws = sm;              // 128*128
    float* Xs = sm + 128 * 128;  // 128 * 66
    const int tid = threadIdx.x;
    const int rbase = blockIdx.x * 64;

    const float4* W4 = (const float4*)W;
    float4* Ws4 = (float4*)Ws;
#pragma unroll
    for (int i = 0; i < 16; i++) Ws4[i * 256 + tid] = W4[i * 256 + tid];

#pragma unroll
    for (int it = 0; it < 32; it++) {
        int idx = it * 256 + tid;
        int r = idx >> 7, k = idx & 127;
        int row = rbase + r;
        Xs[k * 66 + r] = (row < NN) ? x[(size_t)row * 128 + k] : 0.f;
    }
    __syncthreads();

    const int tx = tid & 31, ty = tid >> 5;
    const int cb = tx * 4, rb = ty * 8;
    unsigned long long acc[4][4];
#pragma unroll
    for (int p = 0; p < 4; p++)
#pragma unroll
        for (int c = 0; c < 4; c++) acc[p][c] = 0ull;

#pragma unroll 4
    for (int k = 0; k < 128; k++) {
        float4 w4 = *(const float4*)(Ws + k * 128 + cb);
        unsigned long long wd0 = pack_dup(w4.x), wd1 = pack_dup(w4.y),
                           wd2 = pack_dup(w4.z), wd3 = pack_dup(w4.w);
        const float* xrow = Xs + k * 66 + rb;
#pragma unroll
        for (int p = 0; p < 4; p++) {
            unsigned long long a2 = pack2f(*(const float2*)(xrow + 2 * p));
            fma2(acc[p][0], a2, wd0);
            fma2(acc[p][1], a2, wd1);
            fma2(acc[p][2], a2, wd2);
            fma2(acc[p][3], a2, wd3);
        }
    }

#pragma unroll
    for (int p = 0; p < 4; p++) {
        float2 c0 = unpack2(acc[p][0]), c1 = unpack2(acc[p][1]),
               c2 = unpack2(acc[p][2]), c3 = unpack2(acc[p][3]);
        int row0 = rbase + rb + 2 * p;
        if (row0 < NN) {
            float4 o = make_float4(c0.x, c1.x, c2.x, c3.x);
            *(float4*)&g_xw[(size_t)row0 * 128 + cb] = o;
            uint2 hv; hv.x = h2_from_f2(o.x, o.y); hv.y = h2_from_f2(o.z, o.w);
            *(uint2*)&g_xwh[(size_t)row0 * 128 + cb] = hv;
        }
        int row1 = row0 + 1;
        if (row1 < NN) {
            float4 o = make_float4(c0.y, c1.y, c2.y, c3.y);
            *(float4*)&g_xw[(size_t)row1 * 128 + cb] = o;
            uint2 hv; hv.x = h2_from_f2(o.x, o.y); hv.y = h2_from_f2(o.z, o.w);
            *(uint2*)&g_xwh[(size_t)row1 * 128 + cb] = hv;
        }
    }
}

// ---------------- GEMM2: g_xw[:,0:64] = h @ W2 + fp16 copy (h read as fp16) ----------------
__global__ void k_gemm2(const float* __restrict__ W) {
    extern __shared__ float sm[];
    float* Ws = sm;              // 128*64
    float* Xs = sm + 128 * 64;   // 128 * 66
    const int tid = threadIdx.x;
    const int rbase = blockIdx.x * 64;

    const float4* W4 = (const float4*)W;
    float4* Ws4 = (float4*)Ws;
#pragma unroll
    for (int i = 0; i < 8; i++) Ws4[i * 256 + tid] = W4[i * 256 + tid];

#pragma unroll
    for (int it = 0; it < 32; it++) {
        int idx = it * 256 + tid;
        int r = idx >> 7, k = idx & 127;
        int row = rbase + r;
        Xs[k * 66 + r] = (row < NN) ? __half2float(g_hh[(size_t)row * 128 + k]) : 0.f;
    }
    __syncthreads();

    const int tx = tid & 15, ty = tid >> 4;
    const int cb = tx * 4, rb = ty * 4;
    unsigned long long acc[2][4];
#pragma unroll
    for (int p = 0; p < 2; p++)
#pragma unroll
        for (int c = 0; c < 4; c++) acc[p][c] = 0ull;

#pragma unroll 4
    for (int k = 0; k < 128; k++) {
        float4 w4 = *(const float4*)(Ws + k * 64 + cb);
        unsigned long long wd0 = pack_dup(w4.x), wd1 = pack_dup(w4.y),
                           wd2 = pack_dup(w4.z), wd3 = pack_dup(w4.w);
        const float* xrow = Xs + k * 66 + rb;
#pragma unroll
        for (int p = 0; p < 2; p++) {
            unsigned long long a2 = pack2f(*(const float2*)(xrow + 2 * p));
            fma2(acc[p][0], a2, wd0);
            fma2(acc[p][1], a2, wd1);
            fma2(acc[p][2], a2, wd2);
            fma2(acc[p][3], a2, wd3);
        }
    }

#pragma unroll
    for (int p = 0; p < 2; p++) {
        float2 c0 = unpack2(acc[p][0]), c1 = unpack2(acc[p][1]),
               c2 = unpack2(acc[p][2]), c3 = unpack2(acc[p][3]);
        int row0 = rbase + rb + 2 * p;
        if (row0 < NN) {
            float4 o = make_float4(c0.x, c1.x, c2.x, c3.x);
            *(float4*)&g_xw[(size_t)row0 * 64 + cb] = o;
            uint2 hv; hv.x = h2_from_f2(o.x, o.y); hv.y = h2_from_f2(o.z, o.w);
            *(uint2*)&g_xwh[(size_t)row0 * 64 + cb] = hv;
        }
        int row1 = row0 + 1;
        if (row1 < NN) {
            float4 o = make_float4(c0.y, c1.y, c2.y, c3.y);
            *(float4*)&g_xw[(size_t)row1 * 64 + cb] = o;
            uint2 hv; hv.x = h2_from_f2(o.x, o.y); hv.y = h2_from_f2(o.z, o.w);
            *(uint2*)&g_xwh[(size_t)row1 * 64 + cb] = hv;
        }
    }
}

// ---------------- gather layer 1: warp per dst node, 4-edge unroll; fp16 h output ----------------
__global__ void k_gather1(const float* __restrict__ b, const float* __restrict__ al) {
    int gid = blockIdx.x * 256 + threadIdx.x;   // NN*32 threads exactly
    int node = gid >> 5;
    int lane = gid & 31;
    int beg = g_off[node], end = g_off[node + 1];
    float s = g_dinv1[node];

    // self loop (fp32): xw[node]*dinv^2; one factor here, one in epilogue
    float4 acc = *(const float4*)&g_xw[(size_t)node * 128 + lane * 4];
    acc.x *= s; acc.y *= s; acc.z *= s; acc.w *= s;

    int i = beg;
    for (; i + 3 < end; i += 4) {
        int2 e0 = g_e1[i], e1 = g_e1[i + 1], e2 = g_e1[i + 2], e3 = g_e1[i + 3];
        uint2 u0 = *(const uint2*)&g_xwh[(size_t)e0.x * 128 + lane * 4];
        uint2 u1 = *(const uint2*)&g_xwh[(size_t)e1.x * 128 + lane * 4];
        uint2 u2 = *(const uint2*)&g_xwh[(size_t)e2.x * 128 + lane * 4];
        uint2 u3 = *(const uint2*)&g_xwh[(size_t)e3.x * 128 + lane * 4];
        float w0 = __int_as_float(e0.y), w1 = __int_as_float(e1.y);
        float w2 = __int_as_float(e2.y), w3 = __int_as_float(e3.y);
        float2 p0 = __half22float2(*(__half2*)&u0.x), q0 = __half22float2(*(__half2*)&u0.y);
        float2 p1 = __half22float2(*(__half2*)&u1.x), q1 = __half22float2(*(__half2*)&u1.y);
        float2 p2 = __half22float2(*(__half2*)&u2.x), q2 = __half22float2(*(__half2*)&u2.y);
        float2 p3 = __half22float2(*(__half2*)&u3.x), q3 = __half22float2(*(__half2*)&u3.y);
        acc.x += (w0 * p0.x + w1 * p1.x) + (w2 * p2.x + w3 * p3.x);
        acc.y += (w0 * p0.y + w1 * p1.y) + (w2 * p2.y + w3 * p3.y);
        acc.z += (w0 * q0.x + w1 * q1.x) + (w2 * q2.x + w3 * q3.x);
        acc.w += (w0 * q0.y + w1 * q1.y) + (w2 * q2.y + w3 * q3.y);
    }
    for (; i < end; i++) {
        int2 e0 = g_e1[i];
        uint2 u0 = *(const uint2*)&g_xwh[(size_t)e0.x * 128 + lane * 4];
        float w0 = __int_as_float(e0.y);
        float2 p0 = __half22float2(*(__half2*)&u0.x), q0 = __half22float2(*(__half2*)&u0.y);
        acc.x += w0 * p0.x; acc.y += w0 * p0.y;
        acc.z += w0 * q0.x; acc.w += w0 * q0.y;
    }

    float4 bb = *(const float4*)&b[lane * 4];
    float4 aa = *(const float4*)&al[lane * 4];
    acc.x = acc.x * s + bb.x; acc.y = acc.y * s + bb.y;
    acc.z = acc.z * s + bb.z; acc.w = acc.w * s + bb.w;
    acc.x = (acc.x >= 0.f) ? acc.x : aa.x * acc.x;
    acc.y = (acc.y >= 0.f) ? acc.y : aa.y * acc.y;
    acc.z = (acc.z >= 0.f) ? acc.z : aa.z * acc.z;
    acc.w = (acc.w >= 0.f) ? acc.w : aa.w * acc.w;
    uint2 hv; hv.x = h2_from_f2(acc.x, acc.y); hv.y = h2_from_f2(acc.z, acc.w);
    *(uint2*)&g_hh[(size_t)node * 128 + lane * 4] = hv;
}

// ---------------- gather layer 2 fused with half-combine (4-edge unroll) ----------------
__device__ __forceinline__ float4 gather2_node(int node, int l16) {
    int beg = g_off2[node], end = g_off2[node + 1];
    float s = g_dinv2[node];
    float4 acc = *(const float4*)&g_xw[(size_t)node * 64 + l16 * 4];
    acc.x *= s; acc.y *= s; acc.z *= s; acc.w *= s;

    int i = beg;
    for (; i + 3 < end; i += 4) {
        int2 e0 = g_e2[i], e1 = g_e2[i + 1], e2 = g_e2[i + 2], e3 = g_e2[i + 3];
        uint2 u0 = *(const uint2*)&g_xwh[(size_t)e0.x * 64 + l16 * 4];
        uint2 u1 = *(const uint2*)&g_xwh[(size_t)e1.x * 64 + l16 * 4];
        uint2 u2 = *(const uint2*)&g_xwh[(size_t)e2.x * 64 + l16 * 4];
        uint2 u3 = *(const uint2*)&g_xwh[(size_t)e3.x * 64 + l16 * 4];
        float w0 = __int_as_float(e0.y), w1 = __int_as_float(e1.y);
        float w2 = __int_as_float(e2.y), w3 = __int_as_float(e3.y);
        float2 p0 = __half22float2(*(__half2*)&u0.x), q0 = __half22float2(*(__half2*)&u0.y);
        float2 p1 = __half22float2(*(__half2*)&u1.x), q1 = __half22float2(*(__half2*)&u1.y);
        float2 p2 = __half22float2(*(__half2*)&u2.x), q2 = __half22float2(*(__half2*)&u2.y);
        float2 p3 = __half22float2(*(__half2*)&u3.x), q3 = __half22float2(*(__half2*)&u3.y);
        acc.x += (w0 * p0.x + w1 * p1.x) + (w2 * p2.x + w3 * p3.x);
        acc.y += (w0 * p0.y + w1 * p1.y) + (w2 * p2.y + w3 * p3.y);
        acc.z += (w0 * q0.x + w1 * q1.x) + (w2 * q2.x + w3 * q3.x);
        acc.w += (w0 * q0.y + w1 * q1.y) + (w2 * q2.y + w3 * q3.y);
    }
    for (; i < end; i++) {
        int2 e0 = g_e2[i];
        uint2 u0 = *(const uint2*)&g_xwh[(size_t)e0.x * 64 + l16 * 4];
        float w0 = __int_as_float(e0.y);
        float2 p0 = __half22float2(*(__half2*)&u0.x), q0 = __half22float2(*(__half2*)&u0.y);
        acc.x += w0 * p0.x; acc.y += w0 * p0.y;
        acc.z += w0 * q0.x; acc.w += w0 * q0.y;
    }
    acc.x *= s; acc.y *= s; acc.z *= s; acc.w *= s;
    return acc;
}

__global__ void k_gather2(const float* __restrict__ b, const float* __restrict__ al,
                          float* __restrict__ out) {
    int gid = blockIdx.x * 256 + threadIdx.x;   // HALF*16 threads exactly
    int i = gid >> 4;
    int l16 = gid & 15;

    float4 va = gather2_node(i, l16);
    float4 vb = gather2_node(i + HALF, l16);

    float4 bb = *(const float4*)&b[l16 * 4];
    float4 aa = *(const float4*)&al[l16 * 4];
    va.x += bb.x; va.y += bb.y; va.z += bb.z; va.w += bb.w;
    vb.x += bb.x; vb.y += bb.y; vb.z += bb.z; vb.w += bb.w;
    va.x = (va.x >= 0.f) ? va.x : aa.x * va.x;
    va.y = (va.y >= 0.f) ? va.y : aa.y * va.y;
    va.z = (va.z >= 0.f) ? va.z : aa.z * va.z;
    va.w = (va.w >= 0.f) ? va.w : aa.w * va.w;
    vb.x = (vb.x >= 0.f) ? vb.x : aa.x * vb.x;
    vb.y = (vb.y >= 0.f) ? vb.y : aa.y * vb.y;
    vb.z = (vb.z >= 0.f) ? vb.z : aa.z * vb.z;
    vb.w = (vb.w >= 0.f) ? vb.w : aa.w * vb.w;

    *(float4*)&out[(size_t)i * 64 + l16 * 4] =
        make_float4(0.5f * (va.x + vb.x), 0.5f * (va.y + vb.y),
                    0.5f * (va.z + vb.z), 0.5f * (va.w + vb.w));
}

// ---------------- launch ----------------
extern "C" void kernel_launch(void* const* d_in, const int* in_sizes, int n_in,
                              void* d_out, int out_size) {
    (void)in_sizes; (void)n_in; (void)out_size;
    const float* x   = (const float*)d_in[0];
    const int*   ei  = (const int*)d_in[1];
    const float* ew  = (const float*)d_in[2];
    const int*   et  = (const int*)d_in[3];
    const float* W1  = (const float*)d_in[4];
    const float* b1  = (const float*)d_in[5];
    const float* a1  = (const float*)d_in[6];
    const float* W2  = (const float*)d_in[7];
    const float* b2  = (const float*)d_in[8];
    const float* a2  = (const float*)d_in[9];
    float* out = (float*)d_out;

    const int smem1 = (128 * 128 + 128 * 66) * sizeof(float);   // 99328
    const int smem2 = (128 * 64  + 128 * 66) * sizeof(float);   // 66560
    cudaFuncSetAttribute(k_gemm1, cudaFuncAttributeMaxDynamicSharedMemorySize, smem1);
    cudaFuncSetAttribute(k_gemm2, cudaFuncAttributeMaxDynamicSharedMemorySize, smem2);

    const int gemm_blocks = (NN + 63) / 64;

    static cudaStream_t s2 = nullptr;
    static cudaEvent_t evF = nullptr, evJ = nullptr;
    static bool tried = false;
    if (!tried) {
        tried = true;
        if (cudaStreamCreateWithFlags(&s2, cudaStreamNonBlocking) != cudaSuccess) s2 = nullptr;
        if (s2) {
            if (cudaEventCreateWithFlags(&evF, cudaEventDisableTiming) != cudaSuccess) { s2 = nullptr; }
            else if (cudaEventCreateWithFlags(&evJ, cudaEventDisableTiming) != cudaSuccess) { s2 = nullptr; }
        }
    }

    if (s2) {
        cudaEventRecord(evF, 0);
        cudaStreamWaitEvent(s2, evF, 0);
        // submission order chosen so gemm1 is the 4th launch (ncu captures launch #4)
        k_hist <<<(EE + 255) / 256, 256, 0, s2>>>(ei, ew, et);      // 1
        k_scanA<<<SCAN_BLOCKS, 1024, 0, s2>>>();                    // 2
        k_scanB<<<1, 128, 0, s2>>>();                               // 3
        k_gemm1<<<gemm_blocks, 256, smem1>>>(x, W1);                // 4  <- profiled
        k_scanC<<<SCAN_BLOCKS, 1024, 0, s2>>>();                    // 5
        k_fill <<<(EE + 255) / 256, 256, 0, s2>>>(ei, ew, et);      // 6
        cudaEventRecord(evJ, s2);
        cudaStreamWaitEvent(0, evJ, 0);
    } else {
        k_hist <<<(EE + 255) / 256, 256>>>(ei, ew, et);
        k_scanA<<<SCAN_BLOCKS, 1024>>>();
        k_scanB<<<1, 128>>>();
        k_scanC<<<SCAN_BLOCKS, 1024>>>();
        k_fill <<<(EE + 255) / 256, 256>>>(ei, ew, et);
        k_gemm1<<<gemm_blocks, 256, smem1>>>(x, W1);
    }

    // layer 1 aggregate
    k_gather1<<<NN * 32 / 256, 256>>>(b1, a1);

    // layer 2 (+ fused half-combine)
    k_gemm2<<<gemm_blocks, 256, smem2>>>(W2);
    k_gather2<<<HALF * 16 / 256, 256>>>(b2, a2, out);
}